// round 2
// baseline (speedup 1.0000x reference)
#include <cuda_runtime.h>

#define DD   64
#define HWs  4096
#define DHW  262144

// Scratch (device globals — allocation-free rule)
__device__ float g_xt[(size_t)DHW * 16];        // x transposed to [z,y,x,c]
__device__ float g_off[(size_t)DHW * 81];       // offsets per voxel, channel-fastest

#define FMA4(A_, s_, v_) { (A_)[0] += (s_)*(v_).x; (A_)[1] += (s_)*(v_).y; \
                           (A_)[2] += (s_)*(v_).z; (A_)[3] += (s_)*(v_).w; }

// ---------------------------------------------------------------------------
// Kernel 0: transpose x [c][v] -> xt [v][c]  (channel-last, float4-friendly)
// ---------------------------------------------------------------------------
__global__ void __launch_bounds__(256) k_transpose(const float* __restrict__ x)
{
    int v = blockIdx.x * 256 + threadIdx.x;   // 0..DHW-1
    float vals[16];
#pragma unroll
    for (int c = 0; c < 16; c++)
        vals[c] = x[(size_t)c * DHW + v];
    float4* dst = reinterpret_cast<float4*>(g_xt + (size_t)v * 16);
#pragma unroll
    for (int q = 0; q < 4; q++)
        dst[q] = make_float4(vals[q*4+0], vals[q*4+1], vals[q*4+2], vals[q*4+3]);
}

// ---------------------------------------------------------------------------
// Kernel 1: offset conv (16 -> 81 channels, 3x3x3, pad 1)
// Block: 8x8x8 voxel tile, 512 threads (one voxel per thread).
// SMEM: x patch [16][10][10][10] (64000 B) + weights rearranged
//       ws[chunk(3)][tapc(432)][28 (27 + pad)] (145152 B) = 209152 B
// ---------------------------------------------------------------------------
__global__ void __launch_bounds__(512) k_offconv(const float* __restrict__ x,
                                                 const float* __restrict__ pk)
{
    extern __shared__ float sm[];
    float* xs = sm;            // 16000 floats
    float* ws = sm + 16000;    // 36288 floats
    const int t = threadIdx.x;

    // weights: ws[chunk*12096 + tapc*28 + j] = pk[tapc*81 + chunk*27 + j], pad j=27 with 0
    for (int i = t; i < 36288; i += 512) {
        int chunk = i / 12096;
        int rem   = i - chunk * 12096;
        int tapc  = rem / 28;
        int j     = rem - tapc * 28;
        ws[i] = (j < 27) ? pk[tapc * 81 + chunk * 27 + j] : 0.f;
    }

    const int bz = blockIdx.z * 8, by = blockIdx.y * 8, bx = blockIdx.x * 8;

    // x patch (origin -1, zero outside volume)
    for (int i = t; i < 16000; i += 512) {
        int c  = i / 1000;
        int r  = i - c * 1000;
        int pz = r / 100;
        int rr = r - pz * 100;
        int py = rr / 10;
        int px = rr - py * 10;
        int gz = bz + pz - 1, gy = by + py - 1, gx = bx + px - 1;
        float v = 0.f;
        if ((unsigned)gz < 64u && (unsigned)gy < 64u && (unsigned)gx < 64u)
            v = x[(size_t)c * DHW + gz * HWs + gy * 64 + gx];
        xs[i] = v;
    }
    __syncthreads();

    const int lx = t & 7, ly = (t >> 3) & 7, lz = t >> 6;
    const int vox = (bz + lz) * HWs + (by + ly) * 64 + (bx + lx);
    float* op = g_off + (size_t)vox * 81;

#pragma unroll 1
    for (int chunk = 0; chunk < 3; chunk++) {
        float acc[28];
#pragma unroll
        for (int j = 0; j < 28; j++) acc[j] = 0.f;

        const float* wbase = ws + chunk * 12096;
#pragma unroll 1
        for (int c = 0; c < 16; c++) {
            const float* xb = xs + c * 1000 + lz * 100 + ly * 10 + lx;
#pragma unroll
            for (int dz = 0; dz < 3; dz++)
#pragma unroll
            for (int dy = 0; dy < 3; dy++)
#pragma unroll
            for (int dx = 0; dx < 3; dx++) {
                float xv = xb[dz * 100 + dy * 10 + dx];
                const float4* wp = reinterpret_cast<const float4*>(
                    wbase + ((dz * 9 + dy * 3 + dx) * 16 + c) * 28);
#pragma unroll
                for (int q = 0; q < 7; q++) {
                    float4 w4 = wp[q];
                    FMA4(acc + q * 4, xv, w4);
                }
            }
        }
#pragma unroll
        for (int j = 0; j < 27; j++)
            op[chunk * 27 + j] = acc[j];
    }
}

// ---------------------------------------------------------------------------
// Kernel 2: deformable gather (trilinear) + tap einsum.
// Block: 4(z) x 8(y) x 8(x) voxel tile, 256 threads (one voxel per thread).
// SMEM: x region [11][15][15][16] (158400 B, halo 3 covers |off|<=2, zero-pad
//       outside volume) + kernel weights 27*16*16 (27648 B) = 186048 B.
// Rare |off|>2 taps fall back to exact global-memory path.
// ---------------------------------------------------------------------------
__global__ void __launch_bounds__(256) k_deform(const float* __restrict__ kern,
                                                float* __restrict__ out)
{
    extern __shared__ float sm[];
    float*  xr  = sm;            // 39600 floats
    float*  kws = sm + 39600;    // 6912 floats
    float4* xr4 = reinterpret_cast<float4*>(xr);
    const int t = threadIdx.x;

    for (int i = t; i < 6912; i += 256) kws[i] = kern[i];

    const int bz = blockIdx.z * 4, by = blockIdx.y * 8, bx = blockIdx.x * 8;
    const int roz = bz - 3, roy = by - 3, rox = bx - 3;

    // region load: 11*15*15 points * 4 float4 = 9900 float4
    const float4* xt4 = reinterpret_cast<const float4*>(g_xt);
    for (int u = t; u < 9900; u += 256) {
        int q  = u & 3;
        int p  = u >> 2;
        int rx = p % 15;
        int p2 = p / 15;
        int ry = p2 % 15;
        int rz = p2 / 15;
        int gz = roz + rz, gy = roy + ry, gx = rox + rx;
        float4 v = make_float4(0.f, 0.f, 0.f, 0.f);
        if ((unsigned)gz < 64u && (unsigned)gy < 64u && (unsigned)gx < 64u)
            v = xt4[(size_t)(gz * HWs + gy * 64 + gx) * 4 + q];
        xr4[u] = v;
    }
    __syncthreads();

    const int lx = t & 7, ly = (t >> 3) & 7, lz = t >> 6;   // lz 0..3
    const int pz = bz + lz, py = by + ly, px = bx + lx;
    const int vox = pz * HWs + py * 64 + px;
    const float* offp = g_off + (size_t)vox * 81;

    float o_[16];
#pragma unroll
    for (int o = 0; o < 16; o++) o_[o] = 0.f;

#pragma unroll 1
    for (int k = 0; k < 27; k++) {
        int kd = k / 9;
        int kh = (k - kd * 9) / 3;
        int kw = k - kd * 9 - kh * 3;

        float cz = (float)(pz + kd - 1) + offp[3 * k + 0];
        float cy = (float)(py + kh - 1) + offp[3 * k + 1];
        float cx = (float)(px + kw - 1) + offp[3 * k + 2];

        float z0f = floorf(cz), y0f = floorf(cy), x0f = floorf(cx);
        float fz = cz - z0f, fy = cy - y0f, fx = cx - x0f;
        int z0 = (int)z0f, y0 = (int)y0f, x0 = (int)x0f;
        int lz0 = z0 - roz, ly0 = y0 - roy, lx0 = x0 - rox;

        float a[16];
#pragma unroll
        for (int c = 0; c < 16; c++) a[c] = 0.f;

        if ((unsigned)lz0 <= 9u && (unsigned)ly0 <= 13u && (unsigned)lx0 <= 13u) {
            // fast path: all 8 corners inside smem region (zero-padded OOB)
#pragma unroll
            for (int dz = 0; dz < 2; dz++) {
                float wz = dz ? fz : 1.f - fz;
#pragma unroll
                for (int dy = 0; dy < 2; dy++) {
                    float wzy = wz * (dy ? fy : 1.f - fy);
#pragma unroll
                    for (int dx = 0; dx < 2; dx++) {
                        float wc = wzy * (dx ? fx : 1.f - fx);
                        const float4* v = xr4 +
                            ((lz0 + dz) * 225 + (ly0 + dy) * 15 + (lx0 + dx)) * 4;
                        float4 v0 = v[0], v1 = v[1], v2 = v[2], v3 = v[3];
                        FMA4(a + 0,  wc, v0);
                        FMA4(a + 4,  wc, v1);
                        FMA4(a + 8,  wc, v2);
                        FMA4(a + 12, wc, v3);
                    }
                }
            }
        } else {
            // exact fallback: global reads, validity mask (reference semantics)
#pragma unroll
            for (int dz = 0; dz < 2; dz++) {
                float wz = dz ? fz : 1.f - fz;
#pragma unroll
                for (int dy = 0; dy < 2; dy++) {
                    float wzy = wz * (dy ? fy : 1.f - fy);
#pragma unroll
                    for (int dx = 0; dx < 2; dx++) {
                        int zi = z0 + dz, yi = y0 + dy, xi = x0 + dx;
                        if ((unsigned)zi < 64u && (unsigned)yi < 64u && (unsigned)xi < 64u) {
                            float wc = wzy * (dx ? fx : 1.f - fx);
                            const float4* v = xt4 + (size_t)(zi * HWs + yi * 64 + xi) * 4;
                            float4 v0 = v[0], v1 = v[1], v2 = v[2], v3 = v[3];
                            FMA4(a + 0,  wc, v0);
                            FMA4(a + 4,  wc, v1);
                            FMA4(a + 8,  wc, v2);
                            FMA4(a + 12, wc, v3);
                        }
                    }
                }
            }
        }

        // einsum fold: out[o] += a[c] * kern[k][c][o]
        const float4* kp = reinterpret_cast<const float4*>(kws + k * 256);
#pragma unroll
        for (int c = 0; c < 16; c++) {
            float av = a[c];
            float4 w0 = kp[c * 4 + 0];
            float4 w1 = kp[c * 4 + 1];
            float4 w2 = kp[c * 4 + 2];
            float4 w3 = kp[c * 4 + 3];
            FMA4(o_ + 0,  av, w0);
            FMA4(o_ + 4,  av, w1);
            FMA4(o_ + 8,  av, w2);
            FMA4(o_ + 12, av, w3);
        }
    }

#pragma unroll
    for (int o = 0; o < 16; o++)
        out[(size_t)o * DHW + vox] = o_[o];
}

// ---------------------------------------------------------------------------
extern "C" void kernel_launch(void* const* d_in, const int* in_sizes, int n_in,
                              void* d_out, int out_size)
{
    const float* x    = (const float*)d_in[0];   // [16,64,64,64]
    const float* kern = (const float*)d_in[1];   // [27,16,16]
    const float* pk   = (const float*)d_in[2];   // [27,16,81]
    float* out = (float*)d_out;                  // [16,64,64,64]

    cudaFuncSetAttribute(k_offconv, cudaFuncAttributeMaxDynamicSharedMemorySize, 209152);
    cudaFuncSetAttribute(k_deform,  cudaFuncAttributeMaxDynamicSharedMemorySize, 186048);

    k_transpose<<<1024, 256>>>(x);
    k_offconv<<<dim3(8, 8, 8), 512, 209152>>>(x, pk);
    k_deform<<<dim3(8, 8, 16), 256, 186048>>>(kern, out);
}

// round 3
// speedup vs baseline: 1.2832x; 1.2832x over previous
#include <cuda_runtime.h>

#define HWs  4096
#define DHW  262144

// Scratch (device globals — allocation-free rule)
__device__ float  g_xt[(size_t)DHW * 16];     // x transposed to [z,y,x,c]
__device__ float4 g_off4[(size_t)DHW * 27];   // per-voxel, per-tap (offz,offy,offx,pad)

// ---- packed f32x2 helpers (sm_103a) --------------------------------------
__device__ __forceinline__ unsigned long long pack2(float v) {
    unsigned long long r;
    asm("mov.b64 %0, {%1, %1};" : "=l"(r) : "f"(v));
    return r;
}
__device__ __forceinline__ void fma2(unsigned long long& d,
                                     unsigned long long a, unsigned long long b) {
    asm("fma.rn.f32x2 %0, %1, %2, %0;" : "+l"(d) : "l"(a), "l"(b));
}
__device__ __forceinline__ float2 unpack2(unsigned long long v) {
    float2 f;
    asm("mov.b64 {%0, %1}, %2;" : "=f"(f.x), "=f"(f.y) : "l"(v));
    return f;
}

// ---------------------------------------------------------------------------
// Kernel 0: transpose x [c][v] -> xt [v][c]  (channel-last, float4-friendly)
// ---------------------------------------------------------------------------
__global__ void __launch_bounds__(256) k_transpose(const float* __restrict__ x)
{
    int v = blockIdx.x * 256 + threadIdx.x;
    float vals[16];
#pragma unroll
    for (int c = 0; c < 16; c++)
        vals[c] = x[(size_t)c * DHW + v];
    float4* dst = reinterpret_cast<float4*>(g_xt + (size_t)v * 16);
#pragma unroll
    for (int q = 0; q < 4; q++)
        dst[q] = make_float4(vals[q*4+0], vals[q*4+1], vals[q*4+2], vals[q*4+3]);
}

// ---------------------------------------------------------------------------
// Kernel 1: offset conv (16 -> 81 channels, 3x3x3, pad 1), f32x2 packed.
// Grid (24,8,8): blockIdx.x encodes (x-tile, chunk). Each chunk = 27 output
// channels = taps 9c..9c+8 (3 coords each). 256 threads, 2 voxels/thread
// (z and z+4). SMEM: x patch [16][10][10][10] (64000 B) + this chunk's
// weights ws[432 rows][28] (48384 B) = 112384 B -> 2 blocks/SM.
// ---------------------------------------------------------------------------
__global__ void __launch_bounds__(256) k_offconv(const float* __restrict__ x,
                                                 const float* __restrict__ pk)
{
    extern __shared__ float sm[];
    float* xs = sm;            // 16000 floats
    float* ws = sm + 16000;    // 12096 floats
    const int t = threadIdx.x;

    const int chunk = blockIdx.x % 3;
    const int bx = (blockIdx.x / 3) * 8, by = blockIdx.y * 8, bz = blockIdx.z * 8;

    // weights for this chunk: ws[row*28 + j] = pk[row*81 + chunk*27 + j]
    for (int i = t; i < 12096; i += 256) {
        int row = i / 28;
        int j   = i - row * 28;
        ws[i] = (j < 27) ? pk[row * 81 + chunk * 27 + j] : 0.f;
    }

    // x patch (origin -1, zero outside volume)
    for (int i = t; i < 16000; i += 256) {
        int c  = i / 1000;
        int r  = i - c * 1000;
        int pz = r / 100;
        int rr = r - pz * 100;
        int py = rr / 10;
        int px = rr - py * 10;
        int gz = bz + pz - 1, gy = by + py - 1, gx = bx + px - 1;
        float v = 0.f;
        if ((unsigned)gz < 64u && (unsigned)gy < 64u && (unsigned)gx < 64u)
            v = x[(size_t)c * DHW + gz * HWs + gy * 64 + gx];
        xs[i] = v;
    }
    __syncthreads();

    const int lx = t & 7, ly = (t >> 3) & 7, lz = t >> 6;   // lz 0..3

    unsigned long long acc0[14], acc1[14];
#pragma unroll
    for (int q = 0; q < 14; q++) { acc0[q] = 0ULL; acc1[q] = 0ULL; }

#pragma unroll 1
    for (int c = 0; c < 16; c++) {
        const float* xc = xs + c * 1000 + lz * 100 + ly * 10 + lx;
#pragma unroll
        for (int tap = 0; tap < 27; tap++) {
            const int dz = tap / 9, dy = (tap % 9) / 3, dx = tap % 3;
            const int xo = dz * 100 + dy * 10 + dx;
            float xv0 = xc[xo];
            float xv1 = xc[xo + 400];
            unsigned long long p0 = pack2(xv0);
            unsigned long long p1 = pack2(xv1);
            const ulonglong2* wp = reinterpret_cast<const ulonglong2*>(
                ws + (tap * 16 + c) * 28);
#pragma unroll
            for (int q = 0; q < 7; q++) {
                ulonglong2 w = wp[q];
                fma2(acc0[2*q    ], p0, w.x);
                fma2(acc0[2*q + 1], p0, w.y);
                fma2(acc1[2*q    ], p1, w.x);
                fma2(acc1[2*q + 1], p1, w.y);
            }
        }
    }

    // unpack + store as per-tap float4 (taps 9*chunk .. 9*chunk+8)
    float a0[28], a1[28];
#pragma unroll
    for (int q = 0; q < 14; q++) {
        float2 f0 = unpack2(acc0[q]);  a0[2*q] = f0.x;  a0[2*q+1] = f0.y;
        float2 f1 = unpack2(acc1[q]);  a1[2*q] = f1.x;  a1[2*q+1] = f1.y;
    }
    const int vox0 = (bz + lz) * HWs + (by + ly) * 64 + (bx + lx);
    const int vox1 = vox0 + 4 * HWs;
    float4* op0 = g_off4 + (size_t)vox0 * 27 + chunk * 9;
    float4* op1 = g_off4 + (size_t)vox1 * 27 + chunk * 9;
#pragma unroll
    for (int kl = 0; kl < 9; kl++) {
        op0[kl] = make_float4(a0[3*kl], a0[3*kl+1], a0[3*kl+2], 0.f);
        op1[kl] = make_float4(a1[3*kl], a1[3*kl+1], a1[3*kl+2], 0.f);
    }
}

// ---------------------------------------------------------------------------
// Kernel 2: deformable gather (trilinear) + tap einsum, f32x2 packed.
// Block: 4(z) x 8(y) x 8(x) voxel tile, 256 threads (one voxel per thread).
// SMEM: x region [11][15][15][16] (158400 B) + kernel 27*16*16 (27648 B).
// ---------------------------------------------------------------------------
__global__ void __launch_bounds__(256) k_deform(const float* __restrict__ kern,
                                                float* __restrict__ out)
{
    extern __shared__ float sm[];
    float*  xr  = sm;            // 39600 floats
    float*  kws = sm + 39600;    // 6912 floats
    const int t = threadIdx.x;

    for (int i = t; i < 6912; i += 256) kws[i] = kern[i];

    const int bz = blockIdx.z * 4, by = blockIdx.y * 8, bx = blockIdx.x * 8;
    const int roz = bz - 3, roy = by - 3, rox = bx - 3;

    const float4* xt4 = reinterpret_cast<const float4*>(g_xt);
    float4* xr4 = reinterpret_cast<float4*>(xr);
    for (int u = t; u < 9900; u += 256) {
        int q  = u & 3;
        int p  = u >> 2;
        int rx = p % 15;
        int p2 = p / 15;
        int ry = p2 % 15;
        int rz = p2 / 15;
        int gz = roz + rz, gy = roy + ry, gx = rox + rx;
        float4 v = make_float4(0.f, 0.f, 0.f, 0.f);
        if ((unsigned)gz < 64u && (unsigned)gy < 64u && (unsigned)gx < 64u)
            v = xt4[(size_t)(gz * HWs + gy * 64 + gx) * 4 + q];
        xr4[u] = v;
    }
    __syncthreads();

    const int lx = t & 7, ly = (t >> 3) & 7, lz = t >> 6;   // lz 0..3
    const int pz = bz + lz, py = by + ly, px = bx + lx;
    const int vox = pz * HWs + py * 64 + px;
    const float4* offp = g_off4 + (size_t)vox * 27;

    unsigned long long o2[8];
#pragma unroll
    for (int q = 0; q < 8; q++) o2[q] = 0ULL;

#pragma unroll 1
    for (int k = 0; k < 27; k++) {
        const int kd = k / 9;
        const int kh = (k - kd * 9) / 3;
        const int kw = k - kd * 9 - kh * 3;

        float4 of = offp[k];
        float cz = (float)(pz + kd - 1) + of.x;
        float cy = (float)(py + kh - 1) + of.y;
        float cx = (float)(px + kw - 1) + of.z;

        float z0f = floorf(cz), y0f = floorf(cy), x0f = floorf(cx);
        float fz = cz - z0f, fy = cy - y0f, fx = cx - x0f;
        int z0 = (int)z0f, y0 = (int)y0f, x0 = (int)x0f;
        int lz0 = z0 - roz, ly0 = y0 - roy, lx0 = x0 - rox;

        unsigned long long a2[8];
#pragma unroll
        for (int q = 0; q < 8; q++) a2[q] = 0ULL;

        if ((unsigned)lz0 <= 9u && (unsigned)ly0 <= 13u && (unsigned)lx0 <= 13u) {
            // fast path: all 8 corners inside smem region (zero-padded OOB)
#pragma unroll
            for (int dz = 0; dz < 2; dz++) {
                float wz = dz ? fz : 1.f - fz;
#pragma unroll
                for (int dy = 0; dy < 2; dy++) {
                    float wzy = wz * (dy ? fy : 1.f - fy);
#pragma unroll
                    for (int dx = 0; dx < 2; dx++) {
                        float wc = wzy * (dx ? fx : 1.f - fx);
                        unsigned long long pw = pack2(wc);
                        const ulonglong2* v2 = reinterpret_cast<const ulonglong2*>(
                            xr + ((lz0 + dz) * 225 + (ly0 + dy) * 15 + (lx0 + dx)) * 16);
                        ulonglong2 q0 = v2[0], q1 = v2[1], q2 = v2[2], q3 = v2[3];
                        fma2(a2[0], pw, q0.x); fma2(a2[1], pw, q0.y);
                        fma2(a2[2], pw, q1.x); fma2(a2[3], pw, q1.y);
                        fma2(a2[4], pw, q2.x); fma2(a2[5], pw, q2.y);
                        fma2(a2[6], pw, q3.x); fma2(a2[7], pw, q3.y);
                    }
                }
            }
        } else {
            // exact fallback: global reads, validity mask (reference semantics)
#pragma unroll
            for (int dz = 0; dz < 2; dz++) {
                float wz = dz ? fz : 1.f - fz;
#pragma unroll
                for (int dy = 0; dy < 2; dy++) {
                    float wzy = wz * (dy ? fy : 1.f - fy);
#pragma unroll
                    for (int dx = 0; dx < 2; dx++) {
                        int zi = z0 + dz, yi = y0 + dy, xi = x0 + dx;
                        if ((unsigned)zi < 64u && (unsigned)yi < 64u && (unsigned)xi < 64u) {
                            float wc = wzy * (dx ? fx : 1.f - fx);
                            unsigned long long pw = pack2(wc);
                            const ulonglong2* v2 = reinterpret_cast<const ulonglong2*>(
                                g_xt + (size_t)(zi * HWs + yi * 64 + xi) * 16);
                            ulonglong2 q0 = v2[0], q1 = v2[1], q2 = v2[2], q3 = v2[3];
                            fma2(a2[0], pw, q0.x); fma2(a2[1], pw, q0.y);
                            fma2(a2[2], pw, q1.x); fma2(a2[3], pw, q1.y);
                            fma2(a2[4], pw, q2.x); fma2(a2[5], pw, q2.y);
                            fma2(a2[6], pw, q3.x); fma2(a2[7], pw, q3.y);
                        }
                    }
                }
            }
        }

        // einsum fold: out[o] += a[c] * kern[k][c][o]
#pragma unroll
        for (int cp = 0; cp < 8; cp++) {
            float2 af = unpack2(a2[cp]);
            unsigned long long pa0 = pack2(af.x);
            unsigned long long pa1 = pack2(af.y);
            const ulonglong2* kp0 = reinterpret_cast<const ulonglong2*>(
                kws + k * 256 + (2 * cp) * 16);
            ulonglong2 w0 = kp0[0], w1 = kp0[1], w2 = kp0[2], w3 = kp0[3];
            fma2(o2[0], pa0, w0.x); fma2(o2[1], pa0, w0.y);
            fma2(o2[2], pa0, w1.x); fma2(o2[3], pa0, w1.y);
            fma2(o2[4], pa0, w2.x); fma2(o2[5], pa0, w2.y);
            fma2(o2[6], pa0, w3.x); fma2(o2[7], pa0, w3.y);
            const ulonglong2* kp1 = kp0 + 4;
            ulonglong2 u0 = kp1[0], u1 = kp1[1], u2 = kp1[2], u3 = kp1[3];
            fma2(o2[0], pa1, u0.x); fma2(o2[1], pa1, u0.y);
            fma2(o2[2], pa1, u1.x); fma2(o2[3], pa1, u1.y);
            fma2(o2[4], pa1, u2.x); fma2(o2[5], pa1, u2.y);
            fma2(o2[6], pa1, u3.x); fma2(o2[7], pa1, u3.y);
        }
    }

#pragma unroll
    for (int q = 0; q < 8; q++) {
        float2 f = unpack2(o2[q]);
        out[(size_t)(2*q    ) * DHW + vox] = f.x;
        out[(size_t)(2*q + 1) * DHW + vox] = f.y;
    }
}

// ---------------------------------------------------------------------------
extern "C" void kernel_launch(void* const* d_in, const int* in_sizes, int n_in,
                              void* d_out, int out_size)
{
    const float* x    = (const float*)d_in[0];   // [16,64,64,64]
    const float* kern = (const float*)d_in[1];   // [27,16,16]
    const float* pk   = (const float*)d_in[2];   // [27,16,81]
    float* out = (float*)d_out;                  // [16,64,64,64]

    cudaFuncSetAttribute(k_offconv, cudaFuncAttributeMaxDynamicSharedMemorySize, 112384);
    cudaFuncSetAttribute(k_deform,  cudaFuncAttributeMaxDynamicSharedMemorySize, 186048);

    k_transpose<<<1024, 256>>>(x);
    k_offconv<<<dim3(24, 8, 8), 256, 112384>>>(x, pk);
    k_deform<<<dim3(8, 8, 16), 256, 186048>>>(kern, out);
}

// round 5
// speedup vs baseline: 1.5931x; 1.2415x over previous
#include <cuda_runtime.h>
#include <cstdint>

#define HWs  4096
#define DHW  262144

// ---------------- scratch (device globals; allocation-free rule) -----------
__device__ float  g_xt[(size_t)DHW * 16];     // x transposed to [z,y,x,c]
__device__ float4 g_off4[(size_t)DHW * 27];   // per-voxel per-tap offsets
__device__ float  g_Btf[432 * 104];           // tf32 weights, pitch 104

// ---- packed f32x2 helpers (deform kernel) ----------------------------------
__device__ __forceinline__ unsigned long long pack2(float v) {
    unsigned long long r;
    asm("mov.b64 %0, {%1, %1};" : "=l"(r) : "f"(v));
    return r;
}
__device__ __forceinline__ void fma2(unsigned long long& d,
                                     unsigned long long a, unsigned long long b) {
    asm("fma.rn.f32x2 %0, %1, %2, %0;" : "+l"(d) : "l"(a), "l"(b));
}
__device__ __forceinline__ float2 unpack2(unsigned long long v) {
    float2 f;
    asm("mov.b64 {%0, %1}, %2;" : "=f"(f.x), "=f"(f.y) : "l"(v));
    return f;
}

// ---- misc helpers ----------------------------------------------------------
__device__ __forceinline__ uint32_t smem_u32(const void* p) {
    uint32_t a;
    asm("{ .reg .u64 t; cvta.to.shared.u64 t, %1; cvt.u32.u64 %0, t; }" : "=r"(a) : "l"(p));
    return a;
}
__device__ __forceinline__ uint32_t cvt_tf32(float v) {
    uint32_t u;
    asm("cvt.rna.tf32.f32 %0, %1;" : "=r"(u) : "f"(v));
    return u;
}
__device__ __forceinline__ void cp_async16(uint32_t dst, const void* src) {
    asm volatile("cp.async.ca.shared.global [%0], [%1], 16;" :: "r"(dst), "l"(src) : "memory");
}
__device__ __forceinline__ void mma_tf32(float* d, uint32_t a0, uint32_t a1,
                                         uint32_t a2, uint32_t a3,
                                         uint32_t b0, uint32_t b1) {
    asm volatile(
        "mma.sync.aligned.m16n8k8.row.col.f32.tf32.tf32.f32 "
        "{%0,%1,%2,%3}, {%4,%5,%6,%7}, {%8,%9}, {%0,%1,%2,%3};"
        : "+f"(d[0]), "+f"(d[1]), "+f"(d[2]), "+f"(d[3])
        : "r"(a0), "r"(a1), "r"(a2), "r"(a3), "r"(b0), "r"(b1));
}

// ---------------------------------------------------------------------------
// Prep: pkernel [432 rows (tap*16+c)][81] -> tf32 padded [432][104]
// ---------------------------------------------------------------------------
__global__ void __launch_bounds__(256) k_btf(const float* __restrict__ pk)
{
    int i = blockIdx.x * 256 + threadIdx.x;
    if (i >= 432 * 104) return;
    int k = i / 104, j = i - k * 104;
    float v = (j < 81) ? pk[k * 81 + j] : 0.f;
    g_Btf[i] = __uint_as_float(cvt_tf32(v));
}

// ---------------------------------------------------------------------------
// Kernel 0: transpose x [c][v] -> xt [v][c]
// ---------------------------------------------------------------------------
__global__ void __launch_bounds__(256) k_transpose(const float* __restrict__ x)
{
    int v = blockIdx.x * 256 + threadIdx.x;
    float vals[16];
#pragma unroll
    for (int c = 0; c < 16; c++)
        vals[c] = x[(size_t)c * DHW + v];
    float4* dst = reinterpret_cast<float4*>(g_xt + (size_t)v * 16);
#pragma unroll
    for (int q = 0; q < 4; q++)
        dst[q] = make_float4(vals[q*4+0], vals[q*4+1], vals[q*4+2], vals[q*4+3]);
}

// ---------------------------------------------------------------------------
// Kernel 1: offset GEMM via mma.sync tf32 m16n8k8.
// Block = 128 voxels (z fixed, 2 y-rows, 64 x), 256 threads / 8 warps.
// SMEM: B ring 4 x [8][104] f32 (13312 B) @0, patch [3][4][66][20] f32
//       (63360 B) @13312 (reused as D staging), tap table @76672. 76800 B.
// ---------------------------------------------------------------------------
__global__ void __launch_bounds__(256) k_gemm(const float* __restrict__ x)
{
    extern __shared__ float sm[];
    float* bbuf  = sm;                    // 3328 floats (4 slabs x 832)
    float* patch = sm + 3328;             // 15840 floats
    int*   tapo  = reinterpret_cast<int*>(sm + 3328 + 15840);
    float* stage = patch;                 // reuse after compute

    const int t    = threadIdx.x;
    const int lane = t & 31;
    const int w    = t >> 5;
    const int z    = blockIdx.y;
    const int y0   = blockIdx.x * 2;
    const uint32_t bb = smem_u32(bbuf);

    if (t < 27)
        tapo[t] = (((t / 9) * 4 + (t % 9) / 3) * 66 + (t % 3)) * 20;

    // prefetch B slabs 0..2 (one cp.async group per slab)
#pragma unroll
    for (int s = 0; s < 3; s++) {
        if (t < 208) cp_async16(bb + (s * 832 + t * 4) * 4, g_Btf + s * 832 + t * 4);
        asm volatile("cp.async.commit_group;" ::: "memory");
    }

    // x patch: [pz 0..2][py 0..3][px 0..65][c], pitch-20 channel dim
    for (int j = t; j < 12672; j += 256) {
        int px = j % 66;
        int r  = j / 66;
        int c  = r / 12;
        int q  = r - c * 12;
        int pz = q >> 2, py = q & 3;
        int gz = z - 1 + pz, gy = y0 - 1 + py, gx = px - 1;
        float v = 0.f;
        if ((unsigned)gz < 64u && (unsigned)gy < 64u && (unsigned)gx < 64u)
            v = x[(size_t)c * DHW + gz * HWs + gy * 64 + gx];
        patch[((pz * 4 + py) * 66 + px) * 20 + c] = v;
    }

    // per-thread fragment bases
    const int row0 = (w << 4) + (lane >> 2);
    const int row1 = row0 + 8;
    const int abase0 = (((row0 >> 6) * 66) + (row0 & 63)) * 20 + (lane & 3);
    const int abase1 = (((row1 >> 6) * 66) + (row1 & 63)) * 20 + (lane & 3);
    const int bthr   = (lane & 3) * 104 + (lane >> 2);

    float d[48];
#pragma unroll
    for (int i = 0; i < 48; i++) d[i] = 0.f;

#pragma unroll 1
    for (int kt = 0; kt < 54; kt++) {
        asm volatile("cp.async.wait_group 2;" ::: "memory");
        __syncthreads();
        // issue slab kt+3 into ring slot (kt+3)&3
        if (kt + 3 < 54) {
            if (t < 208)
                cp_async16(bb + (((kt + 3) & 3) * 832 + t * 4) * 4,
                           g_Btf + (kt + 3) * 832 + t * 4);
        }
        asm volatile("cp.async.commit_group;" ::: "memory");

        // A fragments (tap uniform within an 8-k tile)
        const int k0  = kt << 3;
        const int c0  = k0 & 8;
        const int tof = tapo[k0 >> 4] + c0;
        const float* pa0 = patch + abase0 + tof;
        const float* pa1 = patch + abase1 + tof;
        uint32_t a0 = cvt_tf32(pa0[0]);
        uint32_t a2 = cvt_tf32(pa0[4]);
        uint32_t a1 = cvt_tf32(pa1[0]);
        uint32_t a3 = cvt_tf32(pa1[4]);

        const float* bs = bbuf + (kt & 3) * 832 + bthr;
#pragma unroll
        for (int j = 0; j < 12; j++) {
            uint32_t b0 = __float_as_uint(bs[j * 8]);
            uint32_t b1 = __float_as_uint(bs[j * 8 + 416]);
            mma_tf32(d + j * 4, a0, a1, a2, a3, b0, b1);
        }
    }

    asm volatile("cp.async.wait_group 0;" ::: "memory");
    __syncthreads();

    // stage D: [128 vox][pitch 100]
    const int col0 = (lane & 3) * 2;
#pragma unroll
    for (int j = 0; j < 12; j++) {
        stage[row0 * 100 + j * 8 + col0    ] = d[j * 4 + 0];
        stage[row0 * 100 + j * 8 + col0 + 1] = d[j * 4 + 1];
        stage[row1 * 100 + j * 8 + col0    ] = d[j * 4 + 2];
        stage[row1 * 100 + j * 8 + col0 + 1] = d[j * 4 + 3];
    }
    __syncthreads();

    for (int i = t; i < 3456; i += 256) {
        int v   = i / 27;
        int tap = i - v * 27;
        int vox = z * HWs + (y0 + (v >> 6)) * 64 + (v & 63);
        const float* s = stage + v * 100 + 3 * tap;
        g_off4[(size_t)vox * 27 + tap] = make_float4(s[0], s[1], s[2], 0.f);
    }
}

// ---------------------------------------------------------------------------
// Kernel 2: deformable gather (trilinear) + tap einsum (unchanged, passing)
// ---------------------------------------------------------------------------
__global__ void __launch_bounds__(256) k_deform(const float* __restrict__ kern,
                                                float* __restrict__ out)
{
    extern __shared__ float sm[];
    float*  xr  = sm;            // 39600 floats
    float*  kws = sm + 39600;    // 6912 floats
    const int t = threadIdx.x;

    for (int i = t; i < 6912; i += 256) kws[i] = kern[i];

    const int bz = blockIdx.z * 4, by = blockIdx.y * 8, bx = blockIdx.x * 8;
    const int roz = bz - 3, roy = by - 3, rox = bx - 3;

    const float4* xt4 = reinterpret_cast<const float4*>(g_xt);
    float4* xr4 = reinterpret_cast<float4*>(xr);
    for (int u = t; u < 9900; u += 256) {
        int q  = u & 3;
        int p  = u >> 2;
        int rx = p % 15;
        int p2 = p / 15;
        int ry = p2 % 15;
        int rz = p2 / 15;
        int gz = roz + rz, gy = roy + ry, gx = rox + rx;
        float4 v = make_float4(0.f, 0.f, 0.f, 0.f);
        if ((unsigned)gz < 64u && (unsigned)gy < 64u && (unsigned)gx < 64u)
            v = xt4[(size_t)(gz * HWs + gy * 64 + gx) * 4 + q];
        xr4[u] = v;
    }
    __syncthreads();

    const int lx = t & 7, ly = (t >> 3) & 7, lz = t >> 6;
    const int pz = bz + lz, py = by + ly, px = bx + lx;
    const int vox = pz * HWs + py * 64 + px;
    const float4* offp = g_off4 + (size_t)vox * 27;

    unsigned long long o2[8];
#pragma unroll
    for (int q = 0; q < 8; q++) o2[q] = 0ULL;

#pragma unroll 1
    for (int k = 0; k < 27; k++) {
        const int kd = k / 9;
        const int kh = (k - kd * 9) / 3;
        const int kw = k - kd * 9 - kh * 3;

        float4 of = offp[k];
        float cz = (float)(pz + kd - 1) + of.x;
        float cy = (float)(py + kh - 1) + of.y;
        float cx = (float)(px + kw - 1) + of.z;

        float z0f = floorf(cz), y0f = floorf(cy), x0f = floorf(cx);
        float fz = cz - z0f, fy = cy - y0f, fx = cx - x0f;
        int z0 = (int)z0f, y0 = (int)y0f, x0 = (int)x0f;
        int lz0 = z0 - roz, ly0 = y0 - roy, lx0 = x0 - rox;

        unsigned long long a2[8];
#pragma unroll
        for (int q = 0; q < 8; q++) a2[q] = 0ULL;

        if ((unsigned)lz0 <= 9u && (unsigned)ly0 <= 13u && (unsigned)lx0 <= 13u) {
#pragma unroll
            for (int dz = 0; dz < 2; dz++) {
                float wz = dz ? fz : 1.f - fz;
#pragma unroll
                for (int dy = 0; dy < 2; dy++) {
                    float wzy = wz * (dy ? fy : 1.f - fy);
#pragma unroll
                    for (int dx = 0; dx < 2; dx++) {
                        float wc = wzy * (dx ? fx : 1.f - fx);
                        unsigned long long pw = pack2(wc);
                        const ulonglong2* v2 = reinterpret_cast<const ulonglong2*>(
                            xr + ((lz0 + dz) * 225 + (ly0 + dy) * 15 + (lx0 + dx)) * 16);
                        ulonglong2 q0 = v2[0], q1 = v2[1], q2 = v2[2], q3 = v2[3];
                        fma2(a2[0], pw, q0.x); fma2(a2[1], pw, q0.y);
                        fma2(a2[2], pw, q1.x); fma2(a2[3], pw, q1.y);
                        fma2(a2[4], pw, q2.x); fma2(a2[5], pw, q2.y);
                        fma2(a2[6], pw, q3.x); fma2(a2[7], pw, q3.y);
                    }
                }
            }
        } else {
#pragma unroll
            for (int dz = 0; dz < 2; dz++) {
                float wz = dz ? fz : 1.f - fz;
#pragma unroll
                for (int dy = 0; dy < 2; dy++) {
                    float wzy = wz * (dy ? fy : 1.f - fy);
#pragma unroll
                    for (int dx = 0; dx < 2; dx++) {
                        int zi = z0 + dz, yi = y0 + dy, xi = x0 + dx;
                        if ((unsigned)zi < 64u && (unsigned)yi < 64u && (unsigned)xi < 64u) {
                            float wc = wzy * (dx ? fx : 1.f - fx);
                            unsigned long long pw = pack2(wc);
                            const ulonglong2* v2 = reinterpret_cast<const ulonglong2*>(
                                g_xt + (size_t)(zi * HWs + yi * 64 + xi) * 16);
                            ulonglong2 q0 = v2[0], q1 = v2[1], q2 = v2[2], q3 = v2[3];
                            fma2(a2[0], pw, q0.x); fma2(a2[1], pw, q0.y);
                            fma2(a2[2], pw, q1.x); fma2(a2[3], pw, q1.y);
                            fma2(a2[4], pw, q2.x); fma2(a2[5], pw, q2.y);
                            fma2(a2[6], pw, q3.x); fma2(a2[7], pw, q3.y);
                        }
                    }
                }
            }
        }

#pragma unroll
        for (int cp = 0; cp < 8; cp++) {
            float2 af = unpack2(a2[cp]);
            unsigned long long pa0 = pack2(af.x);
            unsigned long long pa1 = pack2(af.y);
            const ulonglong2* kp0 = reinterpret_cast<const ulonglong2*>(
                kws + k * 256 + (2 * cp) * 16);
            ulonglong2 w0 = kp0[0], w1 = kp0[1], w2 = kp0[2], w3 = kp0[3];
            fma2(o2[0], pa0, w0.x); fma2(o2[1], pa0, w0.y);
            fma2(o2[2], pa0, w1.x); fma2(o2[3], pa0, w1.y);
            fma2(o2[4], pa0, w2.x); fma2(o2[5], pa0, w2.y);
            fma2(o2[6], pa0, w3.x); fma2(o2[7], pa0, w3.y);
            const ulonglong2* kp1 = kp0 + 4;
            ulonglong2 u0 = kp1[0], u1 = kp1[1], u2 = kp1[2], u3 = kp1[3];
            fma2(o2[0], pa1, u0.x); fma2(o2[1], pa1, u0.y);
            fma2(o2[2], pa1, u1.x); fma2(o2[3], pa1, u1.y);
            fma2(o2[4], pa1, u2.x); fma2(o2[5], pa1, u2.y);
            fma2(o2[6], pa1, u3.x); fma2(o2[7], pa1, u3.y);
        }
    }

#pragma unroll
    for (int q = 0; q < 8; q++) {
        float2 f = unpack2(o2[q]);
        out[(size_t)(2*q    ) * DHW + vox] = f.x;
        out[(size_t)(2*q + 1) * DHW + vox] = f.y;
    }
}

// ---------------------------------------------------------------------------
extern "C" void kernel_launch(void* const* d_in, const int* in_sizes, int n_in,
                              void* d_out, int out_size)
{
    const float* x    = (const float*)d_in[0];   // [16,64,64,64]
    const float* kern = (const float*)d_in[1];   // [27,16,16]
    const float* pk   = (const float*)d_in[2];   // [27,16,81]
    float* out = (float*)d_out;                  // [16,64,64,64]

    cudaFuncSetAttribute(k_gemm,   cudaFuncAttributeMaxDynamicSharedMemorySize, 76800);
    cudaFuncSetAttribute(k_deform, cudaFuncAttributeMaxDynamicSharedMemorySize, 186048);

    k_btf<<<176, 256>>>(pk);
    k_transpose<<<1024, 256>>>(x);
    k_gemm<<<dim3(32, 64), 256, 76800>>>(x);
    k_deform<<<dim3(8, 8, 16), 256, 186048>>>(kern, out);
}

// round 6
// speedup vs baseline: 2.8535x; 1.7912x over previous
#include <cuda_runtime.h>
#include <cuda_fp16.h>
#include <cstdint>

#define HWs  4096
#define DHW  262144

// ---------------- scratch (device globals; allocation-free rule) -----------
__device__ __half2 g_xth[(size_t)DHW * 8];    // x channel-last fp16 [v][c]
__device__ float4  g_off4[(size_t)DHW * 27];  // per-voxel per-tap offsets
__device__ float   g_Btf[432 * 104];          // tf32 weights, pitch 104

// ---- packed f32x2 helpers ---------------------------------------------------
__device__ __forceinline__ unsigned long long pack2(float v) {
    unsigned long long r;
    asm("mov.b64 %0, {%1, %1};" : "=l"(r) : "f"(v));
    return r;
}
__device__ __forceinline__ void fma2(unsigned long long& d,
                                     unsigned long long a, unsigned long long b) {
    asm("fma.rn.f32x2 %0, %1, %2, %0;" : "+l"(d) : "l"(a), "l"(b));
}
__device__ __forceinline__ float2 unpack2(unsigned long long v) {
    float2 f;
    asm("mov.b64 {%0, %1}, %2;" : "=f"(f.x), "=f"(f.y) : "l"(v));
    return f;
}

// ---- misc helpers ----------------------------------------------------------
__device__ __forceinline__ uint32_t smem_u32(const void* p) {
    uint32_t a;
    asm("{ .reg .u64 t; cvta.to.shared.u64 t, %1; cvt.u32.u64 %0, t; }" : "=r"(a) : "l"(p));
    return a;
}
__device__ __forceinline__ uint32_t cvt_tf32(float v) {
    uint32_t u;
    asm("cvt.rna.tf32.f32 %0, %1;" : "=r"(u) : "f"(v));
    return u;
}
__device__ __forceinline__ void cp_async16(uint32_t dst, const void* src) {
    asm volatile("cp.async.ca.shared.global [%0], [%1], 16;" :: "r"(dst), "l"(src) : "memory");
}
__device__ __forceinline__ void mma_tf32(float* d, uint32_t a0, uint32_t a1,
                                         uint32_t a2, uint32_t a3,
                                         uint32_t b0, uint32_t b1) {
    asm volatile(
        "mma.sync.aligned.m16n8k8.row.col.f32.tf32.tf32.f32 "
        "{%0,%1,%2,%3}, {%4,%5,%6,%7}, {%8,%9}, {%0,%1,%2,%3};"
        : "+f"(d[0]), "+f"(d[1]), "+f"(d[2]), "+f"(d[3])
        : "r"(a0), "r"(a1), "r"(a2), "r"(a3), "r"(b0), "r"(b1));
}

// ---------------------------------------------------------------------------
// Prep: pkernel [432][81] -> tf32 padded [432][104]
// ---------------------------------------------------------------------------
__global__ void __launch_bounds__(256) k_btf(const float* __restrict__ pk)
{
    int i = blockIdx.x * 256 + threadIdx.x;
    if (i >= 432 * 104) return;
    int k = i / 104, j = i - k * 104;
    float v = (j < 81) ? pk[k * 81 + j] : 0.f;
    g_Btf[i] = __uint_as_float(cvt_tf32(v));
}

// ---------------------------------------------------------------------------
// Kernel 0: transpose x [c][v] -> fp16 channel-last [v][c]
// ---------------------------------------------------------------------------
__global__ void __launch_bounds__(256) k_transpose(const float* __restrict__ x)
{
    int v = blockIdx.x * 256 + threadIdx.x;
    float vals[16];
#pragma unroll
    for (int c = 0; c < 16; c++)
        vals[c] = x[(size_t)c * DHW + v];
    __half2 h[8];
#pragma unroll
    for (int i = 0; i < 8; i++)
        h[i] = __floats2half2_rn(vals[2*i], vals[2*i+1]);
    uint4* dst = reinterpret_cast<uint4*>(g_xth + (size_t)v * 8);
    dst[0] = *reinterpret_cast<uint4*>(&h[0]);
    dst[1] = *reinterpret_cast<uint4*>(&h[4]);
}

// ---------------------------------------------------------------------------
// Kernel 1: offset GEMM via mma.sync tf32 m16n8k8 (unchanged from R5).
// ---------------------------------------------------------------------------
__global__ void __launch_bounds__(256) k_gemm(const float* __restrict__ x)
{
    extern __shared__ float sm[];
    float* bbuf  = sm;                    // 3328 floats (4 slabs x 832)
    float* patch = sm + 3328;             // 15840 floats
    int*   tapo  = reinterpret_cast<int*>(sm + 3328 + 15840);
    float* stage = patch;                 // reuse after compute

    const int t    = threadIdx.x;
    const int lane = t & 31;
    const int w    = t >> 5;
    const int z    = blockIdx.y;
    const int y0   = blockIdx.x * 2;
    const uint32_t bb = smem_u32(bbuf);

    if (t < 27)
        tapo[t] = (((t / 9) * 4 + (t % 9) / 3) * 66 + (t % 3)) * 20;

#pragma unroll
    for (int s = 0; s < 3; s++) {
        if (t < 208) cp_async16(bb + (s * 832 + t * 4) * 4, g_Btf + s * 832 + t * 4);
        asm volatile("cp.async.commit_group;" ::: "memory");
    }

    for (int j = t; j < 12672; j += 256) {
        int px = j % 66;
        int r  = j / 66;
        int c  = r / 12;
        int q  = r - c * 12;
        int pz = q >> 2, py = q & 3;
        int gz = z - 1 + pz, gy = y0 - 1 + py, gx = px - 1;
        float v = 0.f;
        if ((unsigned)gz < 64u && (unsigned)gy < 64u && (unsigned)gx < 64u)
            v = x[(size_t)c * DHW + gz * HWs + gy * 64 + gx];
        patch[((pz * 4 + py) * 66 + px) * 20 + c] = v;
    }

    const int row0 = (w << 4) + (lane >> 2);
    const int row1 = row0 + 8;
    const int abase0 = (((row0 >> 6) * 66) + (row0 & 63)) * 20 + (lane & 3);
    const int abase1 = (((row1 >> 6) * 66) + (row1 & 63)) * 20 + (lane & 3);
    const int bthr   = (lane & 3) * 104 + (lane >> 2);

    float d[48];
#pragma unroll
    for (int i = 0; i < 48; i++) d[i] = 0.f;

#pragma unroll 1
    for (int kt = 0; kt < 54; kt++) {
        asm volatile("cp.async.wait_group 2;" ::: "memory");
        __syncthreads();
        if (kt + 3 < 54) {
            if (t < 208)
                cp_async16(bb + (((kt + 3) & 3) * 832 + t * 4) * 4,
                           g_Btf + (kt + 3) * 832 + t * 4);
        }
        asm volatile("cp.async.commit_group;" ::: "memory");

        const int k0  = kt << 3;
        const int c0  = k0 & 8;
        const int tof = tapo[k0 >> 4] + c0;
        const float* pa0 = patch + abase0 + tof;
        const float* pa1 = patch + abase1 + tof;
        uint32_t a0 = cvt_tf32(pa0[0]);
        uint32_t a2 = cvt_tf32(pa0[4]);
        uint32_t a1 = cvt_tf32(pa1[0]);
        uint32_t a3 = cvt_tf32(pa1[4]);

        const float* bs = bbuf + (kt & 3) * 832 + bthr;
#pragma unroll
        for (int j = 0; j < 12; j++) {
            uint32_t b0 = __float_as_uint(bs[j * 8]);
            uint32_t b1 = __float_as_uint(bs[j * 8 + 416]);
            mma_tf32(d + j * 4, a0, a1, a2, a3, b0, b1);
        }
    }

    asm volatile("cp.async.wait_group 0;" ::: "memory");
    __syncthreads();

    const int col0 = (lane & 3) * 2;
#pragma unroll
    for (int j = 0; j < 12; j++) {
        stage[row0 * 100 + j * 8 + col0    ] = d[j * 4 + 0];
        stage[row0 * 100 + j * 8 + col0 + 1] = d[j * 4 + 1];
        stage[row1 * 100 + j * 8 + col0    ] = d[j * 4 + 2];
        stage[row1 * 100 + j * 8 + col0 + 1] = d[j * 4 + 3];
    }
    __syncthreads();

    for (int i = t; i < 3456; i += 256) {
        int v   = i / 27;
        int tap = i - v * 27;
        int vox = z * HWs + (y0 + (v >> 6)) * 64 + (v & 63);
        const float* s = stage + v * 100 + 3 * tap;
        g_off4[(size_t)vox * 27 + tap] = make_float4(s[0], s[1], s[2], 0.f);
    }
}

// ---------------------------------------------------------------------------
// Kernel 2: deformable gather + einsum. fp16 x region in smem (79200 B) +
// fp32 kern (27648 B) = 106848 B -> 2 blocks/SM (occ 25%).
// Per corner: 2x LDS.128 (16 halves), cvt to f32, scalar FFMA accumulation.
// ---------------------------------------------------------------------------
__global__ void __launch_bounds__(256) k_deform(const float* __restrict__ kern,
                                                float* __restrict__ out)
{
    extern __shared__ float sm[];
    __half2* xrh = reinterpret_cast<__half2*>(sm);     // 39600 half2 = 79200 B
    float*   kws = sm + 19800;                         // 6912 floats
    const int t = threadIdx.x;

    for (int i = t; i < 6912; i += 256) kws[i] = kern[i];

    const int bz = blockIdx.z * 4, by = blockIdx.y * 8, bx = blockIdx.x * 8;
    const int roz = bz - 3, roy = by - 3, rox = bx - 3;

    // region: 11*15*15 points x 32 B (2 uint4 each)
    const uint4* xthq = reinterpret_cast<const uint4*>(g_xth);
    uint4* xrq = reinterpret_cast<uint4*>(xrh);
    for (int u = t; u < 4950; u += 256) {
        int q = u & 1;
        int p = u >> 1;
        int rx = p % 15;
        int p2 = p / 15;
        int ry = p2 % 15;
        int rz = p2 / 15;
        int gz = roz + rz, gy = roy + ry, gx = rox + rx;
        uint4 v = make_uint4(0u, 0u, 0u, 0u);
        if ((unsigned)gz < 64u && (unsigned)gy < 64u && (unsigned)gx < 64u)
            v = xthq[(size_t)(gz * HWs + gy * 64 + gx) * 2 + q];
        xrq[p * 2 + q] = v;
    }
    __syncthreads();

    const int lx = t & 7, ly = (t >> 3) & 7, lz = t >> 6;
    const int pz = bz + lz, py = by + ly, px = bx + lx;
    const int vox = pz * HWs + py * 64 + px;
    const float4* offp = g_off4 + (size_t)vox * 27;

    unsigned long long o2[8];
#pragma unroll
    for (int q = 0; q < 8; q++) o2[q] = 0ULL;

#pragma unroll 1
    for (int k = 0; k < 27; k++) {
        const int kd = k / 9;
        const int kh = (k - kd * 9) / 3;
        const int kw = k - kd * 9 - kh * 3;

        float4 of = offp[k];
        float cz = (float)(pz + kd - 1) + of.x;
        float cy = (float)(py + kh - 1) + of.y;
        float cx = (float)(px + kw - 1) + of.z;

        float z0f = floorf(cz), y0f = floorf(cy), x0f = floorf(cx);
        float fz = cz - z0f, fy = cy - y0f, fx = cx - x0f;
        int z0 = (int)z0f, y0 = (int)y0f, x0 = (int)x0f;
        int lz0 = z0 - roz, ly0 = y0 - roy, lx0 = x0 - rox;

        float a[16];
#pragma unroll
        for (int c = 0; c < 16; c++) a[c] = 0.f;

        if ((unsigned)lz0 <= 9u && (unsigned)ly0 <= 13u && (unsigned)lx0 <= 13u) {
            // fast path: corners inside fp16 smem region (zero-padded OOB)
#pragma unroll
            for (int dz = 0; dz < 2; dz++) {
                float wz = dz ? fz : 1.f - fz;
#pragma unroll
                for (int dy = 0; dy < 2; dy++) {
                    float wzy = wz * (dy ? fy : 1.f - fy);
#pragma unroll
                    for (int dx = 0; dx < 2; dx++) {
                        float wc = wzy * (dx ? fx : 1.f - fx);
                        const __half2* hp = xrh +
                            ((lz0 + dz) * 225 + (ly0 + dy) * 15 + (lx0 + dx)) * 8;
                        uint4 r0 = *reinterpret_cast<const uint4*>(hp);
                        uint4 r1 = *reinterpret_cast<const uint4*>(hp + 4);
#pragma unroll
                        for (int q = 0; q < 4; q++) {
                            float2 f0 = __half22float2(*(reinterpret_cast<__half2*>(&r0) + q));
                            float2 f1 = __half22float2(*(reinterpret_cast<__half2*>(&r1) + q));
                            a[2*q    ] += wc * f0.x;  a[2*q + 1] += wc * f0.y;
                            a[2*q + 8] += wc * f1.x;  a[2*q + 9] += wc * f1.y;
                        }
                    }
                }
            }
        } else {
            // exact fallback: fp16 global reads, validity mask
#pragma unroll
            for (int dz = 0; dz < 2; dz++) {
                float wz = dz ? fz : 1.f - fz;
#pragma unroll
                for (int dy = 0; dy < 2; dy++) {
                    float wzy = wz * (dy ? fy : 1.f - fy);
#pragma unroll
                    for (int dx = 0; dx < 2; dx++) {
                        int zi = z0 + dz, yi = y0 + dy, xi = x0 + dx;
                        if ((unsigned)zi < 64u && (unsigned)yi < 64u && (unsigned)xi < 64u) {
                            float wc = wzy * (dx ? fx : 1.f - fx);
                            const __half2* hp = g_xth + (size_t)(zi * HWs + yi * 64 + xi) * 8;
                            uint4 r0 = *reinterpret_cast<const uint4*>(hp);
                            uint4 r1 = *reinterpret_cast<const uint4*>(hp + 4);
#pragma unroll
                            for (int q = 0; q < 4; q++) {
                                float2 f0 = __half22float2(*(reinterpret_cast<__half2*>(&r0) + q));
                                float2 f1 = __half22float2(*(reinterpret_cast<__half2*>(&r1) + q));
                                a[2*q    ] += wc * f0.x;  a[2*q + 1] += wc * f0.y;
                                a[2*q + 8] += wc * f1.x;  a[2*q + 9] += wc * f1.y;
                            }
                        }
                    }
                }
            }
        }

        // einsum fold: out[o] += a[c] * kern[k][c][o]
#pragma unroll
        for (int c = 0; c < 16; c++) {
            unsigned long long pa = pack2(a[c]);
            const ulonglong2* kp = reinterpret_cast<const ulonglong2*>(
                kws + k * 256 + c * 16);
            ulonglong2 w0 = kp[0], w1 = kp[1], w2 = kp[2], w3 = kp[3];
            fma2(o2[0], pa, w0.x); fma2(o2[1], pa, w0.y);
            fma2(o2[2], pa, w1.x); fma2(o2[3], pa, w1.y);
            fma2(o2[4], pa, w2.x); fma2(o2[5], pa, w2.y);
            fma2(o2[6], pa, w3.x); fma2(o2[7], pa, w3.y);
        }
    }

#pragma unroll
    for (int q = 0; q < 8; q++) {
        float2 f = unpack2(o2[q]);
        out[(size_t)(2*q    ) * DHW + vox] = f.x;
        out[(size_t)(2*q + 1) * DHW + vox] = f.y;
    }
}

// ---------------------------------------------------------------------------
extern "C" void kernel_launch(void* const* d_in, const int* in_sizes, int n_in,
                              void* d_out, int out_size)
{
    const float* x    = (const float*)d_in[0];   // [16,64,64,64]
    const float* kern = (const float*)d_in[1];   // [27,16,16]
    const float* pk   = (const float*)d_in[2];   // [27,16,81]
    float* out = (float*)d_out;                  // [16,64,64,64]

    cudaFuncSetAttribute(k_gemm,   cudaFuncAttributeMaxDynamicSharedMemorySize, 76800);
    cudaFuncSetAttribute(k_deform, cudaFuncAttributeMaxDynamicSharedMemorySize, 106848);

    k_btf<<<176, 256>>>(pk);
    k_transpose<<<1024, 256>>>(x);
    k_gemm<<<dim3(32, 64), 256, 76800>>>(x);
    k_deform<<<dim3(8, 8, 16), 256, 106848>>>(kern, out);
}

// round 7
// speedup vs baseline: 3.7399x; 1.3106x over previous
#include <cuda_runtime.h>
#include <cuda_fp16.h>
#include <cstdint>

#define HWs  4096
#define DHW  262144

// ---------------- scratch (device globals; allocation-free rule) -----------
__device__ __half2 g_xth[(size_t)DHW * 8];    // x channel-last fp16 [v][c]
__device__ float4  g_off4[(size_t)DHW * 27];  // per-voxel per-tap offsets
__device__ __half2 g_BfragG[20736];           // gemm W fragments [27][12][32][2]
__device__ __half2 g_BfragD[6912];            // einsum kern frags [27][2][2][32][2]

// ---- helpers ----------------------------------------------------------------
__device__ __forceinline__ uint32_t smem_u32(const void* p) {
    uint32_t a;
    asm("{ .reg .u64 t; cvta.to.shared.u64 t, %1; cvt.u32.u64 %0, t; }" : "=r"(a) : "l"(p));
    return a;
}
__device__ __forceinline__ void mma_f16(float* d, uint32_t a0, uint32_t a1,
                                        uint32_t a2, uint32_t a3,
                                        uint32_t b0, uint32_t b1) {
    asm volatile(
        "mma.sync.aligned.m16n8k16.row.col.f32.f16.f16.f32 "
        "{%0,%1,%2,%3}, {%4,%5,%6,%7}, {%8,%9}, {%0,%1,%2,%3};"
        : "+f"(d[0]), "+f"(d[1]), "+f"(d[2]), "+f"(d[3])
        : "r"(a0), "r"(a1), "r"(a2), "r"(a3), "r"(b0), "r"(b1));
}
#define LDM_X4(r, addr) asm volatile( \
    "ldmatrix.sync.aligned.m8n8.x4.shared.b16 {%0,%1,%2,%3}, [%4];" \
    : "=r"((r)[0]), "=r"((r)[1]), "=r"((r)[2]), "=r"((r)[3]) : "r"(addr))

// ---------------------------------------------------------------------------
// Prep A: gemm W fragments. Layout half2 idx = ((tap*12+nt)*32+l)*2+r
// value = (W[tap*16+c0][n], W[tap*16+c0+1][n]), c0=2(l&3)+8r, n=nt*8+(l>>2)
// ---------------------------------------------------------------------------
__global__ void __launch_bounds__(256) k_bfragG(const float* __restrict__ pk)
{
    int idx = blockIdx.x * 256 + threadIdx.x;     // < 20736
    int tap = idx / 768;
    int rem = idx - tap * 768;
    int nt  = rem >> 6;
    int l   = (rem & 63) >> 1;
    int r   = idx & 1;
    int c0  = 2 * (l & 3) + 8 * r;
    int n   = nt * 8 + (l >> 2);
    float f0 = (n < 81) ? pk[(tap * 16 + c0    ) * 81 + n] : 0.f;
    float f1 = (n < 81) ? pk[(tap * 16 + c0 + 1) * 81 + n] : 0.f;
    g_BfragG[idx] = __floats2half2_rn(f0, f1);
}

// ---------------------------------------------------------------------------
// Prep B: einsum kern fragments, hi/lo split.
// Layout half2 idx = (((tap*2+nt)*2+p)*32+l)*2+r
// value = kern[tap][c0..c0+1][o], c0=2(l&3)+8r, o=nt*8+(l>>2); p=0 hi, p=1 lo
// ---------------------------------------------------------------------------
__global__ void __launch_bounds__(256) k_bfragD(const float* __restrict__ kern)
{
    int idx = blockIdx.x * 256 + threadIdx.x;     // < 6912
    int tap = idx / 256;
    int rem = idx - tap * 256;
    int nt  = rem >> 7;
    int p   = (rem >> 6) & 1;
    int l   = (rem >> 1) & 31;
    int r   = rem & 1;
    int c0  = 2 * (l & 3) + 8 * r;
    int o   = nt * 8 + (l >> 2);
    float k0 = kern[(tap * 16 + c0    ) * 16 + o];
    float k1 = kern[(tap * 16 + c0 + 1) * 16 + o];
    if (p) {
        k0 = k0 - __half2float(__float2half_rn(k0));
        k1 = k1 - __half2float(__float2half_rn(k1));
    }
    g_BfragD[idx] = __floats2half2_rn(k0, k1);
}

// ---------------------------------------------------------------------------
// Kernel 0: transpose x [c][v] -> fp16 channel-last [v][c]
// ---------------------------------------------------------------------------
__global__ void __launch_bounds__(256) k_transpose(const float* __restrict__ x)
{
    int v = blockIdx.x * 256 + threadIdx.x;
    float vals[16];
#pragma unroll
    for (int c = 0; c < 16; c++)
        vals[c] = x[(size_t)c * DHW + v];
    __half2 h[8];
#pragma unroll
    for (int i = 0; i < 8; i++)
        h[i] = __floats2half2_rn(vals[2*i], vals[2*i+1]);
    uint4* dst = reinterpret_cast<uint4*>(g_xth + (size_t)v * 8);
    dst[0] = *reinterpret_cast<uint4*>(&h[0]);
    dst[1] = *reinterpret_cast<uint4*>(&h[4]);
}

// ---------------------------------------------------------------------------
// Kernel 1: offset GEMM, fp16 mma m16n8k16, one k-tile = one tap (16 ch).
// Block = 128 voxels (z fixed, 2 y-rows, 64 x), 256 threads / 8 warps.
// SMEM: Wfrag 82944 B @0 (reused as D stage) + patch fp16 [792 slots][9 half2]
//       28512 B @82944. Total 111456 B.
// ---------------------------------------------------------------------------
__global__ void __launch_bounds__(256) k_gemm(const float* __restrict__ x)
{
    extern __shared__ char smem[];
    uint32_t* patch = reinterpret_cast<uint32_t*>(smem + 82944); // half2 as u32
    const uint2* bfr = reinterpret_cast<const uint2*>(smem);
    float* stage = reinterpret_cast<float*>(smem);

    const int t    = threadIdx.x;
    const int lane = t & 31;
    const int w    = t >> 5;
    const int z    = blockIdx.y;
    const int y0   = blockIdx.x * 2;

    // W fragments -> smem
    {
        float4* bd = reinterpret_cast<float4*>(smem);
        const float4* bs = reinterpret_cast<const float4*>(g_BfragG);
        for (int i = t; i < 5184; i += 256) bd[i] = bs[i];
    }

    // x patch fp16: slot = (pz*4+py)*66+px, 8 half2 + 1 pad (pitch 9)
    for (int j = t; j < 6336; j += 256) {
        int slot = j >> 3, pair = j & 7;
        int px = slot % 66;
        int q  = slot / 66;
        int py = q & 3, pz = q >> 2;
        int gz = z - 1 + pz, gy = y0 - 1 + py, gx = px - 1;
        float f0 = 0.f, f1 = 0.f;
        if ((unsigned)gz < 64u && (unsigned)gy < 64u && (unsigned)gx < 64u) {
            int g = gz * HWs + gy * 64 + gx;
            f0 = x[(size_t)(2 * pair    ) * DHW + g];
            f1 = x[(size_t)(2 * pair + 1) * DHW + g];
        }
        __half2 h = __floats2half2_rn(f0, f1);
        patch[slot * 9 + pair] = *reinterpret_cast<uint32_t*>(&h);
    }
    __syncthreads();

    const int row0 = (w << 4) + (lane >> 2);
    const int row1 = row0 + 8;
    const int ab0  = ((row0 >> 6) * 66 + (row0 & 63)) * 9 + (lane & 3);
    const int ab1  = ((row1 >> 6) * 66 + (row1 & 63)) * 9 + (lane & 3);

    float d[48];
#pragma unroll
    for (int i = 0; i < 48; i++) d[i] = 0.f;

#pragma unroll 1
    for (int tap = 0; tap < 27; tap++) {
        const int kd = tap / 9, kh = (tap / 3) % 3, kw = tap % 3;
        const int aoff = ((kd * 4 + kh) * 66 + kw) * 9;
        uint32_t a0 = patch[ab0 + aoff];
        uint32_t a2 = patch[ab0 + aoff + 4];
        uint32_t a1 = patch[ab1 + aoff];
        uint32_t a3 = patch[ab1 + aoff + 4];
#pragma unroll
        for (int nt = 0; nt < 12; nt++) {
            uint2 b = bfr[(tap * 12 + nt) * 32 + lane];
            mma_f16(d + nt * 4, a0, a1, a2, a3, b.x, b.y);
        }
    }
    __syncthreads();   // W no longer needed; reuse as stage

    // stage D: [128 vox][pitch 100]
    const int col0 = (lane & 3) * 2;
#pragma unroll
    for (int j = 0; j < 12; j++) {
        stage[row0 * 100 + j * 8 + col0    ] = d[j * 4 + 0];
        stage[row0 * 100 + j * 8 + col0 + 1] = d[j * 4 + 1];
        stage[row1 * 100 + j * 8 + col0    ] = d[j * 4 + 2];
        stage[row1 * 100 + j * 8 + col0 + 1] = d[j * 4 + 3];
    }
    __syncthreads();

    for (int i = t; i < 3456; i += 256) {
        int v   = i / 27;
        int tap = i - v * 27;
        int vox = z * HWs + (y0 + (v >> 6)) * 64 + (v & 63);
        const float* s = stage + v * 100 + 3 * tap;
        g_off4[(size_t)vox * 27 + tap] = make_float4(s[0], s[1], s[2], 0.f);
    }
}

// ---------------------------------------------------------------------------
// Kernel 2: deformable gather (fp32 accum over fp16 region) + HMMA einsum.
// Block: 4(z) x 8(y) x 8(x) = 256 voxels, 8 warps; warp = 32 voxels = A rows.
// SMEM: region [9][13][13][16ch fp16] 48672 B @0; kern frags 27648 B @48672;
//       A stage 8 warps x 32 rows x 48 B @76320. Total 88608 B (2 blocks/SM).
// ---------------------------------------------------------------------------
__global__ void __launch_bounds__(256) k_deform(float* __restrict__ out)
{
    extern __shared__ char smem[];
    __half2* xrh = reinterpret_cast<__half2*>(smem);            // 12168 half2
    const uint2* bfr = reinterpret_cast<const uint2*>(smem + 48672);
    const uint32_t smem_base = smem_u32(smem);

    const int t    = threadIdx.x;
    const int lane = t & 31;
    const int w    = t >> 5;

    // kern fragments -> smem
    {
        float4* bd = reinterpret_cast<float4*>(smem + 48672);
        const float4* bs = reinterpret_cast<const float4*>(g_BfragD);
        for (int i = t; i < 1728; i += 256) bd[i] = bs[i];
    }

    const int bz = blockIdx.z * 4, by = blockIdx.y * 8, bx = blockIdx.x * 8;
    const int roz = bz - 2, roy = by - 2, rox = bx - 2;

    // region: 9*13*13 = 1521 points x 32 B
    {
        const uint4* xthq = reinterpret_cast<const uint4*>(g_xth);
        uint4* xrq = reinterpret_cast<uint4*>(smem);
        for (int u = t; u < 3042; u += 256) {
            int q = u & 1;
            int p = u >> 1;
            int rx = p % 13;
            int p2 = p / 13;
            int ry = p2 % 13;
            int rz = p2 / 13;
            int gz = roz + rz, gy = roy + ry, gx = rox + rx;
            uint4 v = make_uint4(0u, 0u, 0u, 0u);
            if ((unsigned)gz < 64u && (unsigned)gy < 64u && (unsigned)gx < 64u)
                v = xthq[(size_t)(gz * HWs + gy * 64 + gx) * 2 + q];
            xrq[p * 2 + q] = v;
        }
    }
    __syncthreads();

    const int lx = t & 7, ly = (t >> 3) & 7, lz = t >> 6;
    const int pz = bz + lz, py = by + ly, px = bx + lx;
    const int vox = pz * HWs + py * 64 + px;
    const float4* offp = g_off4 + (size_t)vox * 27;

    // A-stage pointers (per-warp, row = lane, pitch 48 B)
    const uint32_t asb = 76320u + (uint32_t)w * 1536u;
    uint4* myrow = reinterpret_cast<uint4*>(smem + asb + lane * 48);
    const uint32_t addrA0 = smem_base + asb + (uint32_t)(lane & 15) * 48u
                          + (uint32_t)(lane >> 4) * 16u;
    const uint32_t addrA1 = addrA0 + 768u;   // mtile 1: rows +16

    float d[16];
#pragma unroll
    for (int q = 0; q < 16; q++) d[q] = 0.f;

#pragma unroll 1
    for (int k = 0; k < 27; k++) {
        const int kd = k / 9;
        const int kh = (k - kd * 9) / 3;
        const int kw = k - kd * 9 - kh * 3;

        float4 of = offp[k];
        float cz = (float)(pz + kd - 1) + of.x;
        float cy = (float)(py + kh - 1) + of.y;
        float cx = (float)(px + kw - 1) + of.z;

        float z0f = floorf(cz), y0f = floorf(cy), x0f = floorf(cx);
        float fz = cz - z0f, fy = cy - y0f, fx = cx - x0f;
        int z0 = (int)z0f, y0 = (int)y0f, x0 = (int)x0f;
        int lz0 = z0 - roz, ly0 = y0 - roy, lx0 = x0 - rox;

        float a[16];
#pragma unroll
        for (int c = 0; c < 16; c++) a[c] = 0.f;

        if ((unsigned)lz0 <= 7u && (unsigned)ly0 <= 11u && (unsigned)lx0 <= 11u) {
            // fast path: corners inside fp16 smem region (zero-padded OOB)
#pragma unroll
            for (int dz = 0; dz < 2; dz++) {
                float wz = dz ? fz : 1.f - fz;
#pragma unroll
                for (int dy = 0; dy < 2; dy++) {
                    float wzy = wz * (dy ? fy : 1.f - fy);
#pragma unroll
                    for (int dx = 0; dx < 2; dx++) {
                        float wc = wzy * (dx ? fx : 1.f - fx);
                        const __half2* hp = xrh +
                            ((lz0 + dz) * 169 + (ly0 + dy) * 13 + (lx0 + dx)) * 8;
                        uint4 r0 = *reinterpret_cast<const uint4*>(hp);
                        uint4 r1 = *reinterpret_cast<const uint4*>(hp + 4);
#pragma unroll
                        for (int q = 0; q < 4; q++) {
                            float2 f0 = __half22float2(*(reinterpret_cast<__half2*>(&r0) + q));
                            float2 f1 = __half22float2(*(reinterpret_cast<__half2*>(&r1) + q));
                            a[2*q    ] += wc * f0.x;  a[2*q + 1] += wc * f0.y;
                            a[2*q + 8] += wc * f1.x;  a[2*q + 9] += wc * f1.y;
                        }
                    }
                }
            }
        } else {
            // exact fallback: fp16 global reads, validity mask
#pragma unroll
            for (int dz = 0; dz < 2; dz++) {
                float wz = dz ? fz : 1.f - fz;
#pragma unroll
                for (int dy = 0; dy < 2; dy++) {
                    float wzy = wz * (dy ? fy : 1.f - fy);
#pragma unroll
                    for (int dx = 0; dx < 2; dx++) {
                        int zi = z0 + dz, yi = y0 + dy, xi = x0 + dx;
                        if ((unsigned)zi < 64u && (unsigned)yi < 64u && (unsigned)xi < 64u) {
                            float wc = wzy * (dx ? fx : 1.f - fx);
                            const __half2* hp = g_xth + (size_t)(zi * HWs + yi * 64 + xi) * 8;
                            uint4 r0 = *reinterpret_cast<const uint4*>(hp);
                            uint4 r1 = *reinterpret_cast<const uint4*>(hp + 4);
#pragma unroll
                            for (int q = 0; q < 4; q++) {
                                float2 f0 = __half22float2(*(reinterpret_cast<__half2*>(&r0) + q));
                                float2 f1 = __half22float2(*(reinterpret_cast<__half2*>(&r1) + q));
                                a[2*q    ] += wc * f0.x;  a[2*q + 1] += wc * f0.y;
                                a[2*q + 8] += wc * f1.x;  a[2*q + 9] += wc * f1.y;
                            }
                        }
                    }
                }
            }
        }

        // ---- einsum via HMMA: stage a -> ldmatrix -> mma ----
        __half2 h[8];
#pragma unroll
        for (int j = 0; j < 8; j++)
            h[j] = __floats2half2_rn(a[2*j], a[2*j+1]);
        __syncwarp();                       // WAR vs previous tap's ldmatrix
        myrow[0] = *reinterpret_cast<uint4*>(&h[0]);
        myrow[1] = *reinterpret_cast<uint4*>(&h[4]);
        __syncwarp();                       // RAW
        uint32_t A0[4], A1[4];
        LDM_X4(A0, addrA0);
        LDM_X4(A1, addrA1);
#pragma unroll
        for (int nt = 0; nt < 2; nt++) {
#pragma unroll
            for (int p = 0; p < 2; p++) {
                uint2 b = bfr[((k * 2 + nt) * 2 + p) * 32 + lane];
                mma_f16(d + nt * 4,     A0[0], A0[1], A0[2], A0[3], b.x, b.y);
                mma_f16(d + 8 + nt * 4, A1[0], A1[1], A1[2], A1[3], b.x, b.y);
            }
        }
    }

    // ---- write out: D[mt][nt] rows = warp voxels, cols = out channels ----
    const int rlo = lane >> 2;
    const int o0  = 2 * (lane & 3);
#pragma unroll
    for (int mt = 0; mt < 2; mt++) {
#pragma unroll
        for (int nt = 0; nt < 2; nt++) {
            const float* dd = d + mt * 8 + nt * 4;
            int vlo = mt * 16 + rlo;
            int vhi = vlo + 8;
            int vox_lo = (bz + (w >> 1)) * HWs
                       + (by + (w & 1) * 4 + (vlo >> 3)) * 64 + bx + (vlo & 7);
            int vox_hi = (bz + (w >> 1)) * HWs
                       + (by + (w & 1) * 4 + (vhi >> 3)) * 64 + bx + (vhi & 7);
            out[(size_t)(nt * 8 + o0    ) * DHW + vox_lo] = dd[0];
            out[(size_t)(nt * 8 + o0 + 1) * DHW + vox_lo] = dd[1];
            out[(size_t)(nt * 8 + o0    ) * DHW + vox_hi] = dd[2];
            out[(size_t)(nt * 8 + o0 + 1) * DHW + vox_hi] = dd[3];
        }
    }
}

// ---------------------------------------------------------------------------
extern "C" void kernel_launch(void* const* d_in, const int* in_sizes, int n_in,
                              void* d_out, int out_size)
{
    const float* x    = (const float*)d_in[0];   // [16,64,64,64]
    const float* kern = (const float*)d_in[1];   // [27,16,16]
    const float* pk   = (const float*)d_in[2];   // [27,16,81]
    float* out = (float*)d_out;                  // [16,64,64,64]

    cudaFuncSetAttribute(k_gemm,   cudaFuncAttributeMaxDynamicSharedMemorySize, 111456);
    cudaFuncSetAttribute(k_deform, cudaFuncAttributeMaxDynamicSharedMemorySize, 88608);

    k_bfragG<<<81, 256>>>(pk);
    k_bfragD<<<27, 256>>>(kern);
    k_transpose<<<1024, 256>>>(x);
    k_gemm<<<dim3(32, 64), 256, 111456>>>(x);
    k_deform<<<dim3(8, 8, 16), 256, 88608>>>(out);
}

// round 8
// speedup vs baseline: 4.2437x; 1.1347x over previous
#include <cuda_runtime.h>
#include <cuda_fp16.h>
#include <cstdint>

#define HWs  4096
#define DHW  262144

// ---------------- scratch (device globals; allocation-free rule) -----------
__device__ __half2 g_xth[(size_t)DHW * 8];    // x channel-last fp16 [v][c]
__device__ float4  g_off4[(size_t)DHW * 27];  // per-voxel per-tap offsets
__device__ uint4   g_BfragG[5184];            // gemm W frags [27][6][32] uint4
__device__ uint2   g_BfragD[1728];            // einsum kern frags [27][2][32] uint2

// ---- helpers ----------------------------------------------------------------
__device__ __forceinline__ uint32_t smem_u32(const void* p) {
    uint32_t a;
    asm("{ .reg .u64 t; cvta.to.shared.u64 t, %1; cvt.u32.u64 %0, t; }" : "=r"(a) : "l"(p));
    return a;
}
__device__ __forceinline__ void mma_f16(float* d, uint32_t a0, uint32_t a1,
                                        uint32_t a2, uint32_t a3,
                                        uint32_t b0, uint32_t b1) {
    asm volatile(
        "mma.sync.aligned.m16n8k16.row.col.f32.f16.f16.f32 "
        "{%0,%1,%2,%3}, {%4,%5,%6,%7}, {%8,%9}, {%0,%1,%2,%3};"
        : "+f"(d[0]), "+f"(d[1]), "+f"(d[2]), "+f"(d[3])
        : "r"(a0), "r"(a1), "r"(a2), "r"(a3), "r"(b0), "r"(b1));
}
#define LDM_X4(r, addr) asm volatile( \
    "ldmatrix.sync.aligned.m8n8.x4.shared.b16 {%0,%1,%2,%3}, [%4];" \
    : "=r"((r)[0]), "=r"((r)[1]), "=r"((r)[2]), "=r"((r)[3]) : "r"(addr))

// ---------------------------------------------------------------------------
// Prep A: gemm W fragments as uint4 = {nt=2np:(r0,r1), nt=2np+1:(r0,r1)}
// r0: channels c0,c0+1 ; r1: c0+8,c0+9 ; c0=2(l&3); n = nt*8 + (l>>2)
// ---------------------------------------------------------------------------
__global__ void __launch_bounds__(256) k_bfragG(const float* __restrict__ pk)
{
    int idx = blockIdx.x * 256 + threadIdx.x;     // < 5184
    if (idx >= 5184) return;
    int tap = idx / 192;
    int rem = idx - tap * 192;
    int np  = rem >> 5;
    int l   = rem & 31;
    int c0  = 2 * (l & 3);
    int n0  = 16 * np + (l >> 2);
    int n1  = n0 + 8;
    int kb  = tap * 16;
    float a0 = (n0 < 81) ? pk[(kb + c0    ) * 81 + n0] : 0.f;
    float a1 = (n0 < 81) ? pk[(kb + c0 + 1) * 81 + n0] : 0.f;
    float b0 = (n0 < 81) ? pk[(kb + c0 + 8) * 81 + n0] : 0.f;
    float b1 = (n0 < 81) ? pk[(kb + c0 + 9) * 81 + n0] : 0.f;
    float c2 = (n1 < 81) ? pk[(kb + c0    ) * 81 + n1] : 0.f;
    float c3 = (n1 < 81) ? pk[(kb + c0 + 1) * 81 + n1] : 0.f;
    float d2 = (n1 < 81) ? pk[(kb + c0 + 8) * 81 + n1] : 0.f;
    float d3 = (n1 < 81) ? pk[(kb + c0 + 9) * 81 + n1] : 0.f;
    __half2 h0 = __floats2half2_rn(a0, a1);
    __half2 h1 = __floats2half2_rn(b0, b1);
    __half2 h2 = __floats2half2_rn(c2, c3);
    __half2 h3 = __floats2half2_rn(d2, d3);
    g_BfragG[idx] = make_uint4(*reinterpret_cast<uint32_t*>(&h0),
                               *reinterpret_cast<uint32_t*>(&h1),
                               *reinterpret_cast<uint32_t*>(&h2),
                               *reinterpret_cast<uint32_t*>(&h3));
}

// ---------------------------------------------------------------------------
// Prep B: einsum kern fragments, single fp16. [(tap*2+nt)*32+l] uint2
// ---------------------------------------------------------------------------
__global__ void __launch_bounds__(256) k_bfragD(const float* __restrict__ kern)
{
    int idx = blockIdx.x * 256 + threadIdx.x;     // < 1728
    if (idx >= 1728) return;
    int tap = idx / 64;
    int nt  = (idx >> 5) & 1;
    int l   = idx & 31;
    int c0  = 2 * (l & 3);
    int o   = nt * 8 + (l >> 2);
    int kb  = tap * 16;
    __half2 h0 = __floats2half2_rn(kern[(kb + c0    ) * 16 + o],
                                   kern[(kb + c0 + 1) * 16 + o]);
    __half2 h1 = __floats2half2_rn(kern[(kb + c0 + 8) * 16 + o],
                                   kern[(kb + c0 + 9) * 16 + o]);
    g_BfragD[idx] = make_uint2(*reinterpret_cast<uint32_t*>(&h0),
                               *reinterpret_cast<uint32_t*>(&h1));
}

// ---------------------------------------------------------------------------
// Kernel 0: transpose x [c][v] -> fp16 channel-last [v][c]
// ---------------------------------------------------------------------------
__global__ void __launch_bounds__(256) k_transpose(const float* __restrict__ x)
{
    int v = blockIdx.x * 256 + threadIdx.x;
    float vals[16];
#pragma unroll
    for (int c = 0; c < 16; c++)
        vals[c] = x[(size_t)c * DHW + v];
    __half2 h[8];
#pragma unroll
    for (int i = 0; i < 8; i++)
        h[i] = __floats2half2_rn(vals[2*i], vals[2*i+1]);
    uint4* dst = reinterpret_cast<uint4*>(g_xth + (size_t)v * 8);
    dst[0] = *reinterpret_cast<uint4*>(&h[0]);
    dst[1] = *reinterpret_cast<uint4*>(&h[4]);
}

// ---------------------------------------------------------------------------
// Kernel 1: offset GEMM. Block = 256 voxels (z fixed, 4 y-rows, 64 x),
// 256 thr / 8 warps; warp = 32 voxels = 2 m16-tiles, all 96 N.
// SMEM: B frag ring (14 taps, 43008 B) @0; patch [3][6][66] slots x 48B
//       (57024 B) @43008. Stage (51200 B) reuses @0. Total 100032 B.
// ---------------------------------------------------------------------------
__global__ void __launch_bounds__(256) k_gemm(const float* __restrict__ x)
{
    extern __shared__ char smem[];
    const uint32_t smem_base = smem_u32(smem);
    uint4* bsm = reinterpret_cast<uint4*>(smem);               // B frags
    uint32_t* patch = reinterpret_cast<uint32_t*>(smem + 43008);
    float* stage = reinterpret_cast<float*>(smem);

    const int t    = threadIdx.x;
    const int lane = t & 31;
    const int w    = t >> 5;
    const int z    = blockIdx.y;
    const int y0   = blockIdx.x * 4;

    // phase-0 B frags (taps 0..13)
    for (int i = t; i < 2688; i += 256) bsm[i] = g_BfragG[i];

    // x patch fp16: slot = (pz*6+py)*66+px, 8 half2 @ pitch 12 u32 (48 B)
    for (int j = t; j < 9504; j += 256) {
        int pair = j / 1188;
        int slot = j - pair * 1188;
        int px = slot % 66;
        int q  = slot / 66;
        int py = q % 6, pz = q / 6;
        int gz = z - 1 + pz, gy = y0 - 1 + py, gx = px - 1;
        float f0 = 0.f, f1 = 0.f;
        if ((unsigned)gz < 64u && (unsigned)gy < 64u && (unsigned)gx < 64u) {
            int g = gz * HWs + gy * 64 + gx;
            f0 = x[(size_t)(2 * pair    ) * DHW + g];
            f1 = x[(size_t)(2 * pair + 1) * DHW + g];
        }
        __half2 h = __floats2half2_rn(f0, f1);
        patch[slot * 12 + pair] = *reinterpret_cast<uint32_t*>(&h);
    }
    __syncthreads();

    // ldmatrix lane address bases (per m-tile)
    const int rowInTile = (lane & 7) + ((lane >> 3) & 1) * 8;
    const int khalf = lane >> 4;
    uint32_t abase[2];
#pragma unroll
    for (int mt = 0; mt < 2; mt++) {
        int r  = w * 32 + mt * 16 + rowInTile;
        int sy = r >> 6, sx = r & 63;
        abase[mt] = smem_base + 43008u + (uint32_t)((sy * 66 + sx) * 48) + khalf * 16u;
    }

    float d[96];
#pragma unroll
    for (int i = 0; i < 96; i++) d[i] = 0.f;

#pragma unroll 1
    for (int phase = 0; phase < 2; phase++) {
        const int t0 = phase ? 14 : 0;
        const int t1 = phase ? 27 : 14;
        if (phase) {
            __syncthreads();
            for (int i = t; i < 2496; i += 256) bsm[i] = g_BfragG[2688 + i];
            __syncthreads();
        }
#pragma unroll 1
        for (int tap = t0; tap < t1; tap++) {
            const int kd = tap / 9, kh = (tap / 3) % 3, kw = tap % 3;
            const uint32_t aoff = (uint32_t)(((kd * 6 + kh) * 66 + kw) * 48);
            uint32_t A0[4], A1[4];
            LDM_X4(A0, abase[0] + aoff);
            LDM_X4(A1, abase[1] + aoff);
            const uint4* bp = bsm + (tap - t0) * 192 + lane;
#pragma unroll
            for (int np = 0; np < 6; np++) {
                uint4 b = bp[np * 32];
                float* d0 = d + (np * 4    ) * 4;   // nt=2np,  mt0
                float* d1 = d + (np * 4 + 1) * 4;   // nt=2np,  mt1
                float* d2 = d + (np * 4 + 2) * 4;   // nt=2np+1,mt0
                float* d3 = d + (np * 4 + 3) * 4;   // nt=2np+1,mt1
                mma_f16(d0, A0[0], A0[1], A0[2], A0[3], b.x, b.y);
                mma_f16(d1, A1[0], A1[1], A1[2], A1[3], b.x, b.y);
                mma_f16(d2, A0[0], A0[1], A0[2], A0[3], b.z, b.w);
                mma_f16(d3, A1[0], A1[1], A1[2], A1[3], b.z, b.w);
            }
        }
    }
    __syncthreads();   // B + patch dead; reuse as stage

    // two half-block passes: stage 128 voxels, then scatter to g_off4
    const int rlo  = lane >> 2;
    const int col0 = 2 * (lane & 3);
#pragma unroll 1
    for (int h = 0; h < 2; h++) {
        if ((w >> 2) == h) {
#pragma unroll
            for (int mt = 0; mt < 2; mt++) {
#pragma unroll
                for (int nt = 0; nt < 12; nt++) {
                    const float* dd = d + ((nt >> 1) * 4 + (nt & 1) * 2 + mt) * 4;
                    int lr0 = (w - h * 4) * 32 + mt * 16 + rlo;
                    stage[lr0 * 100 + nt * 8 + col0    ] = dd[0];
                    stage[lr0 * 100 + nt * 8 + col0 + 1] = dd[1];
                    stage[(lr0 + 8) * 100 + nt * 8 + col0    ] = dd[2];
                    stage[(lr0 + 8) * 100 + nt * 8 + col0 + 1] = dd[3];
                }
            }
        }
        __syncthreads();
        for (int i = t; i < 3456; i += 256) {
            int v   = i / 27;
            int tap = i - v * 27;
            int r   = h * 128 + v;
            int vox = z * HWs + (y0 + (r >> 6)) * 64 + (r & 63);
            const float* s = stage + v * 100 + 3 * tap;
            g_off4[(size_t)vox * 27 + tap] = make_float4(s[0], s[1], s[2], 0.f);
        }
        __syncthreads();
    }
}

// ---------------------------------------------------------------------------
// Kernel 2: deformable gather (full half2 interp) + HMMA einsum.
// Block: 4x8x8 = 256 voxels, 8 warps. SMEM: region [9][13][13][16ch fp16]
// 48672 B @0; kern frags 13824 B @48672; A stage 12288 B @62496 = 74784 B
// -> 3 blocks/SM.
// ---------------------------------------------------------------------------
__global__ void __launch_bounds__(256, 3) k_deform(float* __restrict__ out)
{
    extern __shared__ char smem[];
    __half2* xrh = reinterpret_cast<__half2*>(smem);            // 12168 half2
    const uint2* bfr = reinterpret_cast<const uint2*>(smem + 48672);
    const uint32_t smem_base = smem_u32(smem);

    const int t    = threadIdx.x;
    const int lane = t & 31;
    const int w    = t >> 5;

    // kern fragments -> smem (1728 uint2 = 864 uint4)
    {
        uint4* bd = reinterpret_cast<uint4*>(smem + 48672);
        const uint4* bs = reinterpret_cast<const uint4*>(g_BfragD);
        for (int i = t; i < 864; i += 256) bd[i] = bs[i];
    }

    const int bz = blockIdx.z * 4, by = blockIdx.y * 8, bx = blockIdx.x * 8;
    const int roz = bz - 2, roy = by - 2, rox = bx - 2;

    // region: 9*13*13 = 1521 points x 32 B
    {
        const uint4* xthq = reinterpret_cast<const uint4*>(g_xth);
        uint4* xrq = reinterpret_cast<uint4*>(smem);
        for (int u = t; u < 3042; u += 256) {
            int q = u & 1;
            int p = u >> 1;
            int rx = p % 13;
            int p2 = p / 13;
            int ry = p2 % 13;
            int rz = p2 / 13;
            int gz = roz + rz, gy = roy + ry, gx = rox + rx;
            uint4 v = make_uint4(0u, 0u, 0u, 0u);
            if ((unsigned)gz < 64u && (unsigned)gy < 64u && (unsigned)gx < 64u)
                v = xthq[(size_t)(gz * HWs + gy * 64 + gx) * 2 + q];
            xrq[p * 2 + q] = v;
        }
    }
    __syncthreads();

    const int lx = t & 7, ly = (t >> 3) & 7, lz = t >> 6;
    const int pz = bz + lz, py = by + ly, px = bx + lx;
    const int vox = pz * HWs + py * 64 + px;
    const float4* offp = g_off4 + (size_t)vox * 27;

    // A-stage pointers (per-warp, row = lane, pitch 48 B)
    const uint32_t asb = 62496u + (uint32_t)w * 1536u;
    uint4* myrow = reinterpret_cast<uint4*>(smem + asb + lane * 48);
    const uint32_t addrA0 = smem_base + asb + (uint32_t)(lane & 15) * 48u
                          + (uint32_t)(lane >> 4) * 16u;
    const uint32_t addrA1 = addrA0 + 768u;

    float d[16];
#pragma unroll
    for (int q = 0; q < 16; q++) d[q] = 0.f;

#pragma unroll 1
    for (int k = 0; k < 27; k++) {
        const int kd = k / 9;
        const int kh = (k - kd * 9) / 3;
        const int kw = k - kd * 9 - kh * 3;

        float4 of = offp[k];
        float cz = (float)(pz + kd - 1) + of.x;
        float cy = (float)(py + kh - 1) + of.y;
        float cx = (float)(px + kw - 1) + of.z;

        float z0f = floorf(cz), y0f = floorf(cy), x0f = floorf(cx);
        float fz = cz - z0f, fy = cy - y0f, fx = cx - x0f;
        int z0 = (int)z0f, y0 = (int)y0f, x0 = (int)x0f;
        int lz0 = z0 - roz, ly0 = y0 - roy, lx0 = x0 - rox;

        const __half2 wx0h = __float2half2_rn(1.f - fx);
        const __half2 wx1h = __float2half2_rn(fx);

        __half2 ah[8];
#pragma unroll
        for (int j = 0; j < 8; j++) ah[j] = __float2half2_rn(0.f);

        if ((unsigned)lz0 <= 7u && (unsigned)ly0 <= 11u && (unsigned)lx0 <= 11u) {
            // fast path: both x-corners inside region (zero-padded OOB)
#pragma unroll
            for (int dz = 0; dz < 2; dz++) {
                float wz = dz ? fz : 1.f - fz;
#pragma unroll
                for (int dy = 0; dy < 2; dy++) {
                    __half2 wzyh = __float2half2_rn(wz * (dy ? fy : 1.f - fy));
                    const __half2* hp = xrh +
                        ((lz0 + dz) * 169 + (ly0 + dy) * 13 + lx0) * 8;
                    uint4 p0 = *reinterpret_cast<const uint4*>(hp);
                    uint4 p1 = *reinterpret_cast<const uint4*>(hp + 4);
                    uint4 q0 = *reinterpret_cast<const uint4*>(hp + 8);
                    uint4 q1 = *reinterpret_cast<const uint4*>(hp + 12);
#pragma unroll
                    for (int j = 0; j < 4; j++) {
                        __half2 pj = *(reinterpret_cast<__half2*>(&p0) + j);
                        __half2 qj = *(reinterpret_cast<__half2*>(&q0) + j);
                        __half2 tj = __hfma2(qj, wx1h, __hmul2(pj, wx0h));
                        ah[j] = __hfma2(tj, wzyh, ah[j]);
                        __half2 pk2 = *(reinterpret_cast<__half2*>(&p1) + j);
                        __half2 qk2 = *(reinterpret_cast<__half2*>(&q1) + j);
                        __half2 uk = __hfma2(qk2, wx1h, __hmul2(pk2, wx0h));
                        ah[j + 4] = __hfma2(uk, wzyh, ah[j + 4]);
                    }
                }
            }
        } else {
            // exact fallback: per-corner validity, global fp16 reads
#pragma unroll
            for (int dz = 0; dz < 2; dz++) {
                float wz = dz ? fz : 1.f - fz;
#pragma unroll
                for (int dy = 0; dy < 2; dy++) {
                    __half2 wzyh = __float2half2_rn(wz * (dy ? fy : 1.f - fy));
                    int zi = z0 + dz, yi = y0 + dy;
                    bool okzy = ((unsigned)zi < 64u) && ((unsigned)yi < 64u);
                    uint4 p0 = make_uint4(0,0,0,0), p1 = p0, q0 = p0, q1 = p0;
                    if (okzy && (unsigned)x0 < 64u) {
                        const uint4* g = reinterpret_cast<const uint4*>(
                            g_xth + (size_t)(zi * HWs + yi * 64 + x0) * 8);
                        p0 = g[0]; p1 = g[1];
                    }
                    if (okzy && (unsigned)(x0 + 1) < 64u) {
                        const uint4* g = reinterpret_cast<const uint4*>(
                            g_xth + (size_t)(zi * HWs + yi * 64 + x0 + 1) * 8);
                        q0 = g[0]; q1 = g[1];
                    }
#pragma unroll
                    for (int j = 0; j < 4; j++) {
                        __half2 pj = *(reinterpret_cast<__half2*>(&p0) + j);
                        __half2 qj = *(reinterpret_cast<__half2*>(&q0) + j);
                        __half2 tj = __hfma2(qj, wx1h, __hmul2(pj, wx0h));
                        ah[j] = __hfma2(tj, wzyh, ah[j]);
                        __half2 pk2 = *(reinterpret_cast<__half2*>(&p1) + j);
                        __half2 qk2 = *(reinterpret_cast<__half2*>(&q1) + j);
                        __half2 uk = __hfma2(qk2, wx1h, __hmul2(pk2, wx0h));
                        ah[j + 4] = __hfma2(uk, wzyh, ah[j + 4]);
                    }
                }
            }
        }

        // ---- einsum via HMMA: stage ah -> ldmatrix -> mma ----
        __syncwarp();                       // WAR vs previous tap's ldmatrix
        myrow[0] = *reinterpret_cast<uint4*>(&ah[0]);
        myrow[1] = *reinterpret_cast<uint4*>(&ah[4]);
        __syncwarp();                       // RAW
        uint32_t A0[4], A1[4];
        LDM_X4(A0, addrA0);
        LDM_X4(A1, addrA1);
#pragma unroll
        for (int nt = 0; nt < 2; nt++) {
            uint2 b = bfr[(k * 2 + nt) * 32 + lane];
            mma_f16(d + nt * 4,     A0[0], A0[1], A0[2], A0[3], b.x, b.y);
            mma_f16(d + 8 + nt * 4, A1[0], A1[1], A1[2], A1[3], b.x, b.y);
        }
    }

    // ---- write out ----
    const int rlo = lane >> 2;
    const int o0  = 2 * (lane & 3);
#pragma unroll
    for (int mt = 0; mt < 2; mt++) {
#pragma unroll
        for (int nt = 0; nt < 2; nt++) {
            const float* dd = d + mt * 8 + nt * 4;
            int vlo = mt * 16 + rlo;
            int vhi = vlo + 8;
            int vox_lo = (bz + (w >> 1)) * HWs
                       + (by + (w & 1) * 4 + (vlo >> 3)) * 64 + bx + (vlo & 7);
            int vox_hi = (bz + (w >> 1)) * HWs
                       + (by + (w & 1) * 4 + (vhi >> 3)) * 64 + bx + (vhi & 7);
            out[(size_t)(nt * 8 + o0    ) * DHW + vox_lo] = dd[0];
            out[(size_t)(nt * 8 + o0 + 1) * DHW + vox_lo] = dd[1];
            out[(size_t)(nt * 8 + o0    ) * DHW + vox_hi] = dd[2];
            out[(size_t)(nt * 8 + o0 + 1) * DHW + vox_hi] = dd[3];
        }
    }
}

// ---------------------------------------------------------------------------
extern "C" void kernel_launch(void* const* d_in, const int* in_sizes, int n_in,
                              void* d_out, int out_size)
{
    const float* x    = (const float*)d_in[0];   // [16,64,64,64]
    const float* kern = (const float*)d_in[1];   // [27,16,16]
    const float* pk   = (const float*)d_in[2];   // [27,16,81]
    float* out = (float*)d_out;                  // [16,64,64,64]

    cudaFuncSetAttribute(k_gemm,   cudaFuncAttributeMaxDynamicSharedMemorySize, 100032);
    cudaFuncSetAttribute(k_deform, cudaFuncAttributeMaxDynamicSharedMemorySize, 74784);

    k_bfragG<<<21, 256>>>(pk);
    k_bfragD<<<7, 256>>>(kern);
    k_transpose<<<1024, 256>>>(x);
    k_gemm<<<dim3(16, 64), 256, 100032>>>(x);
    k_deform<<<dim3(8, 8, 16), 256, 74784>>>(out);
}

// round 9
// speedup vs baseline: 4.3282x; 1.0199x over previous
#include <cuda_runtime.h>
#include <cuda_fp16.h>
#include <cstdint>

#define HWs  4096
#define DHW  262144

// ---------------- scratch (device globals; allocation-free rule) -----------
__device__ __half2 g_xth[(size_t)DHW * 8];    // x channel-last fp16 [v][c]
__device__ float4  g_off4[(size_t)DHW * 27];  // per-voxel per-tap offsets
__device__ uint4   g_BfragG[5184];            // gemm W frags [27][6][32] uint4
__device__ uint4   g_BfragD[864];             // einsum kern frags [27][32] uint4

// ---- helpers ----------------------------------------------------------------
__device__ __forceinline__ uint32_t smem_u32(const void* p) {
    uint32_t a;
    asm("{ .reg .u64 t; cvta.to.shared.u64 t, %1; cvt.u32.u64 %0, t; }" : "=r"(a) : "l"(p));
    return a;
}
__device__ __forceinline__ void mma_f16(float* d, uint32_t a0, uint32_t a1,
                                        uint32_t a2, uint32_t a3,
                                        uint32_t b0, uint32_t b1) {
    asm volatile(
        "mma.sync.aligned.m16n8k16.row.col.f32.f16.f16.f32 "
        "{%0,%1,%2,%3}, {%4,%5,%6,%7}, {%8,%9}, {%0,%1,%2,%3};"
        : "+f"(d[0]), "+f"(d[1]), "+f"(d[2]), "+f"(d[3])
        : "r"(a0), "r"(a1), "r"(a2), "r"(a3), "r"(b0), "r"(b1));
}
#define LDM_X4(r, addr) asm volatile( \
    "ldmatrix.sync.aligned.m8n8.x4.shared.b16 {%0,%1,%2,%3}, [%4];" \
    : "=r"((r)[0]), "=r"((r)[1]), "=r"((r)[2]), "=r"((r)[3]) : "r"(addr))

// ---------------------------------------------------------------------------
// Prep A: gemm W fragments as uint4 = {nt=2np:(r0,r1), nt=2np+1:(r0,r1)}
// ---------------------------------------------------------------------------
__global__ void __launch_bounds__(256) k_bfragG(const float* __restrict__ pk)
{
    int idx = blockIdx.x * 256 + threadIdx.x;     // < 5184
    if (idx >= 5184) return;
    int tap = idx / 192;
    int rem = idx - tap * 192;
    int np  = rem >> 5;
    int l   = rem & 31;
    int c0  = 2 * (l & 3);
    int n0  = 16 * np + (l >> 2);
    int n1  = n0 + 8;
    int kb  = tap * 16;
    float a0 = (n0 < 81) ? pk[(kb + c0    ) * 81 + n0] : 0.f;
    float a1 = (n0 < 81) ? pk[(kb + c0 + 1) * 81 + n0] : 0.f;
    float b0 = (n0 < 81) ? pk[(kb + c0 + 8) * 81 + n0] : 0.f;
    float b1 = (n0 < 81) ? pk[(kb + c0 + 9) * 81 + n0] : 0.f;
    float c2 = (n1 < 81) ? pk[(kb + c0    ) * 81 + n1] : 0.f;
    float c3 = (n1 < 81) ? pk[(kb + c0 + 1) * 81 + n1] : 0.f;
    float d2 = (n1 < 81) ? pk[(kb + c0 + 8) * 81 + n1] : 0.f;
    float d3 = (n1 < 81) ? pk[(kb + c0 + 9) * 81 + n1] : 0.f;
    __half2 h0 = __floats2half2_rn(a0, a1);
    __half2 h1 = __floats2half2_rn(b0, b1);
    __half2 h2 = __floats2half2_rn(c2, c3);
    __half2 h3 = __floats2half2_rn(d2, d3);
    g_BfragG[idx] = make_uint4(*reinterpret_cast<uint32_t*>(&h0),
                               *reinterpret_cast<uint32_t*>(&h1),
                               *reinterpret_cast<uint32_t*>(&h2),
                               *reinterpret_cast<uint32_t*>(&h3));
}

// ---------------------------------------------------------------------------
// Prep B: einsum kern fragments as uint4 {nt0:(lo,hi), nt1:(lo,hi)}
// ---------------------------------------------------------------------------
__global__ void __launch_bounds__(256) k_bfragD(const float* __restrict__ kern)
{
    int idx = blockIdx.x * 256 + threadIdx.x;     // < 864
    if (idx >= 864) return;
    int tap = idx >> 5;
    int l   = idx & 31;
    int c0  = 2 * (l & 3);
    int o0  = l >> 2;
    int kb  = tap * 16;
    __half2 h0 = __floats2half2_rn(kern[(kb + c0    ) * 16 + o0],
                                   kern[(kb + c0 + 1) * 16 + o0]);
    __half2 h1 = __floats2half2_rn(kern[(kb + c0 + 8) * 16 + o0],
                                   kern[(kb + c0 + 9) * 16 + o0]);
    __half2 h2 = __floats2half2_rn(kern[(kb + c0    ) * 16 + o0 + 8],
                                   kern[(kb + c0 + 1) * 16 + o0 + 8]);
    __half2 h3 = __floats2half2_rn(kern[(kb + c0 + 8) * 16 + o0 + 8],
                                   kern[(kb + c0 + 9) * 16 + o0 + 8]);
    g_BfragD[idx] = make_uint4(*reinterpret_cast<uint32_t*>(&h0),
                               *reinterpret_cast<uint32_t*>(&h1),
                               *reinterpret_cast<uint32_t*>(&h2),
                               *reinterpret_cast<uint32_t*>(&h3));
}

// ---------------------------------------------------------------------------
// Kernel 0: transpose x [c][v] -> fp16 channel-last [v][c]
// ---------------------------------------------------------------------------
__global__ void __launch_bounds__(256) k_transpose(const float* __restrict__ x)
{
    int v = blockIdx.x * 256 + threadIdx.x;
    float vals[16];
#pragma unroll
    for (int c = 0; c < 16; c++)
        vals[c] = x[(size_t)c * DHW + v];
    __half2 h[8];
#pragma unroll
    for (int i = 0; i < 8; i++)
        h[i] = __floats2half2_rn(vals[2*i], vals[2*i+1]);
    uint4* dst = reinterpret_cast<uint4*>(g_xth + (size_t)v * 8);
    dst[0] = *reinterpret_cast<uint4*>(&h[0]);
    dst[1] = *reinterpret_cast<uint4*>(&h[4]);
}

// ---------------------------------------------------------------------------
// Kernel 1: offset GEMM. Block = 128 voxels (z fixed, 2 y-rows, 64 x),
// 256 thr / 8 warps; warp = (m-group 0..3) x (N-half 0..1): 2 m16 tiles, 48 N.
// SMEM: B phase buf (9 taps, 27648 B) @0; patch [3][4][66] slots x 48 B
//       (38016 B) @27648. Stage (51200 B) reuses @0. Total 65664 B -> 3/SM.
// ---------------------------------------------------------------------------
__global__ void __launch_bounds__(256, 3) k_gemm(const float* __restrict__ x)
{
    extern __shared__ char smem[];
    const uint32_t smem_base = smem_u32(smem);
    uint4* bsm = reinterpret_cast<uint4*>(smem);               // B frags
    uint32_t* patch = reinterpret_cast<uint32_t*>(smem + 27648);
    float* stage = reinterpret_cast<float*>(smem);

    const int t    = threadIdx.x;
    const int lane = t & 31;
    const int w    = t >> 5;
    const int mg    = w >> 1;      // m-group: 32 voxels
    const int nhalf = w & 1;       // N half: np 3*nhalf..3*nhalf+2
    const int z    = blockIdx.y;
    const int y0   = blockIdx.x * 2;

    // x patch fp16: slot = (pz*4+py)*66+px, 8 half2 @ pitch 12 u32 (48 B)
    for (int j = t; j < 6336; j += 256) {
        int pair = j / 792;
        int slot = j - pair * 792;
        int px = slot % 66;
        int q  = slot / 66;
        int py = q & 3, pz = q >> 2;
        int gz = z - 1 + pz, gy = y0 - 1 + py, gx = px - 1;
        float f0 = 0.f, f1 = 0.f;
        if ((unsigned)gz < 64u && (unsigned)gy < 64u && (unsigned)gx < 64u) {
            int g = gz * HWs + gy * 64 + gx;
            f0 = x[(size_t)(2 * pair    ) * DHW + g];
            f1 = x[(size_t)(2 * pair + 1) * DHW + g];
        }
        __half2 h = __floats2half2_rn(f0, f1);
        patch[slot * 12 + pair] = *reinterpret_cast<uint32_t*>(&h);
    }

    // ldmatrix lane address bases (per m-tile)
    const int rowInTile = (lane & 7) + ((lane >> 3) & 1) * 8;
    const int khalf = lane >> 4;
    uint32_t abase[2];
#pragma unroll
    for (int mt = 0; mt < 2; mt++) {
        int r  = mg * 32 + mt * 16 + rowInTile;
        int sy = r >> 6, sx = r & 63;
        abase[mt] = smem_base + 27648u + (uint32_t)((sy * 66 + sx) * 48) + khalf * 16u;
    }

    float d[48];
#pragma unroll
    for (int i = 0; i < 48; i++) d[i] = 0.f;

#pragma unroll 1
    for (int phase = 0; phase < 3; phase++) {
        if (phase) __syncthreads();          // prev-phase B reads done
        for (int i = t; i < 1728; i += 256)
            bsm[i] = g_BfragG[phase * 1728 + i];
        __syncthreads();
#pragma unroll 1
        for (int tl = 0; tl < 9; tl++) {
            const int tap = phase * 9 + tl;
            const int kd = tap / 9, kh = (tap / 3) % 3, kw = tap % 3;
            const uint32_t aoff = (uint32_t)(((kd * 4 + kh) * 66 + kw) * 48);
            uint32_t A0[4], A1[4];
            LDM_X4(A0, abase[0] + aoff);
            LDM_X4(A1, abase[1] + aoff);
            const uint4* bp = bsm + tl * 192 + nhalf * 96 + lane;
#pragma unroll
            for (int np = 0; np < 3; np++) {
                uint4 b = bp[np * 32];
                float* d0 = d + (np * 4    ) * 4;   // nt=2np,  mt0
                float* d1 = d + (np * 4 + 1) * 4;   // nt=2np,  mt1
                float* d2 = d + (np * 4 + 2) * 4;   // nt=2np+1,mt0
                float* d3 = d + (np * 4 + 3) * 4;   // nt=2np+1,mt1
                mma_f16(d0, A0[0], A0[1], A0[2], A0[3], b.x, b.y);
                mma_f16(d1, A1[0], A1[1], A1[2], A1[3], b.x, b.y);
                mma_f16(d2, A0[0], A0[1], A0[2], A0[3], b.z, b.w);
                mma_f16(d3, A1[0], A1[1], A1[2], A1[3], b.z, b.w);
            }
        }
    }
    __syncthreads();   // B + patch dead; reuse as stage

    // stage D: [128 vox][pitch 100]; warps write disjoint (mg, nhalf) regions
    const int rlo  = lane >> 2;
    const int col0 = 2 * (lane & 3);
#pragma unroll
    for (int mt = 0; mt < 2; mt++) {
#pragma unroll
        for (int np = 0; np < 3; np++) {
#pragma unroll
            for (int ntl = 0; ntl < 2; ntl++) {
                const float* dd = d + ((np * 2 + ntl) * 2 + mt) * 4;
                int lr0 = mg * 32 + mt * 16 + rlo;
                int col = (2 * (nhalf * 3 + np) + ntl) * 8 + col0;
                stage[lr0 * 100 + col    ] = dd[0];
                stage[lr0 * 100 + col + 1] = dd[1];
                stage[(lr0 + 8) * 100 + col    ] = dd[2];
                stage[(lr0 + 8) * 100 + col + 1] = dd[3];
            }
        }
    }
    __syncthreads();

    for (int i = t; i < 3456; i += 256) {
        int v   = i / 27;
        int tap = i - v * 27;
        int vox = z * HWs + (y0 + (v >> 6)) * 64 + (v & 63);
        const float* s = stage + v * 100 + 3 * tap;
        g_off4[(size_t)vox * 27 + tap] = make_float4(s[0], s[1], s[2], 0.f);
    }
}

// ---------------------------------------------------------------------------
// Kernel 2: deformable gather (full half2 interp) + HMMA einsum.
// Block: 4x8x8 = 256 voxels, 8 warps. SMEM: region [9][13][13][16ch fp16]
// 48672 B @0; kern frags 13824 B @48672; A stage 12288 B @62496 = 74784 B
// -> 3 blocks/SM.
// ---------------------------------------------------------------------------
__global__ void __launch_bounds__(256, 3) k_deform(float* __restrict__ out)
{
    extern __shared__ char smem[];
    __half2* xrh = reinterpret_cast<__half2*>(smem);            // 12168 half2
    const uint4* bfr = reinterpret_cast<const uint4*>(smem + 48672);
    const uint32_t smem_base = smem_u32(smem);

    const int t    = threadIdx.x;
    const int lane = t & 31;
    const int w    = t >> 5;

    // kern fragments -> smem (864 uint4)
    {
        uint4* bd = reinterpret_cast<uint4*>(smem + 48672);
        for (int i = t; i < 864; i += 256) bd[i] = g_BfragD[i];
    }

    const int bz = blockIdx.z * 4, by = blockIdx.y * 8, bx = blockIdx.x * 8;
    const int roz = bz - 2, roy = by - 2, rox = bx - 2;

    // region: 9*13*13 = 1521 points x 32 B
    {
        const uint4* xthq = reinterpret_cast<const uint4*>(g_xth);
        uint4* xrq = reinterpret_cast<uint4*>(smem);
        for (int u = t; u < 3042; u += 256) {
            int q = u & 1;
            int p = u >> 1;
            int rx = p % 13;
            int p2 = p / 13;
            int ry = p2 % 13;
            int rz = p2 / 13;
            int gz = roz + rz, gy = roy + ry, gx = rox + rx;
            uint4 v = make_uint4(0u, 0u, 0u, 0u);
            if ((unsigned)gz < 64u && (unsigned)gy < 64u && (unsigned)gx < 64u)
                v = xthq[(size_t)(gz * HWs + gy * 64 + gx) * 2 + q];
            xrq[p * 2 + q] = v;
        }
    }
    __syncthreads();

    const int lx = t & 7, ly = (t >> 3) & 7, lz = t >> 6;
    const int pz = bz + lz, py = by + ly, px = bx + lx;
    const int vox = pz * HWs + py * 64 + px;
    const float4* offp = g_off4 + (size_t)vox * 27;

    // A-stage pointers (per-warp, row = lane, pitch 48 B)
    const uint32_t asb = 62496u + (uint32_t)w * 1536u;
    uint4* myrow = reinterpret_cast<uint4*>(smem + asb + lane * 48);
    const uint32_t addrA0 = smem_base + asb + (uint32_t)(lane & 15) * 48u
                          + (uint32_t)(lane >> 4) * 16u;
    const uint32_t addrA1 = addrA0 + 768u;

    float d[16];
#pragma unroll
    for (int q = 0; q < 16; q++) d[q] = 0.f;

#pragma unroll 1
    for (int k = 0; k < 27; k++) {
        const int kd = k / 9;
        const int kh = (k - kd * 9) / 3;
        const int kw = k - kd * 9 - kh * 3;

        float4 of = offp[k];
        float cz = (float)(pz + kd - 1) + of.x;
        float cy = (float)(py + kh - 1) + of.y;
        float cx = (float)(px + kw - 1) + of.z;

        float z0f = floorf(cz), y0f = floorf(cy), x0f = floorf(cx);
        float fz = cz - z0f, fy = cy - y0f, fx = cx - x0f;
        int z0 = (int)z0f, y0 = (int)y0f, x0 = (int)x0f;
        int lz0 = z0 - roz, ly0 = y0 - roy, lx0 = x0 - rox;

        const __half2 wx0h = __float2half2_rn(1.f - fx);
        const __half2 wx1h = __float2half2_rn(fx);

        __half2 ah[8];
#pragma unroll
        for (int j = 0; j < 8; j++) ah[j] = __float2half2_rn(0.f);

        if ((unsigned)lz0 <= 7u && (unsigned)ly0 <= 11u && (unsigned)lx0 <= 11u) {
            // fast path: both x-corners inside region (zero-padded OOB)
#pragma unroll
            for (int dz = 0; dz < 2; dz++) {
                float wz = dz ? fz : 1.f - fz;
#pragma unroll
                for (int dy = 0; dy < 2; dy++) {
                    __half2 wzyh = __float2half2_rn(wz * (dy ? fy : 1.f - fy));
                    const __half2* hp = xrh +
                        ((lz0 + dz) * 169 + (ly0 + dy) * 13 + lx0) * 8;
                    uint4 p0 = *reinterpret_cast<const uint4*>(hp);
                    uint4 p1 = *reinterpret_cast<const uint4*>(hp + 4);
                    uint4 q0 = *reinterpret_cast<const uint4*>(hp + 8);
                    uint4 q1 = *reinterpret_cast<const uint4*>(hp + 12);
#pragma unroll
                    for (int j = 0; j < 4; j++) {
                        __half2 pj = *(reinterpret_cast<__half2*>(&p0) + j);
                        __half2 qj = *(reinterpret_cast<__half2*>(&q0) + j);
                        __half2 tj = __hfma2(qj, wx1h, __hmul2(pj, wx0h));
                        ah[j] = __hfma2(tj, wzyh, ah[j]);
                        __half2 pk2 = *(reinterpret_cast<__half2*>(&p1) + j);
                        __half2 qk2 = *(reinterpret_cast<__half2*>(&q1) + j);
                        __half2 uk = __hfma2(qk2, wx1h, __hmul2(pk2, wx0h));
                        ah[j + 4] = __hfma2(uk, wzyh, ah[j + 4]);
                    }
                }
            }
        } else {
            // exact fallback: per-corner validity, global fp16 reads
#pragma unroll
            for (int dz = 0; dz < 2; dz++) {
                float wz = dz ? fz : 1.f - fz;
#pragma unroll
                for (int dy = 0; dy < 2; dy++) {
                    __half2 wzyh = __float2half2_rn(wz * (dy ? fy : 1.f - fy));
                    int zi = z0 + dz, yi = y0 + dy;
                    bool okzy = ((unsigned)zi < 64u) && ((unsigned)yi < 64u);
                    uint4 p0 = make_uint4(0,0,0,0), p1 = p0, q0 = p0, q1 = p0;
                    if (okzy && (unsigned)x0 < 64u) {
                        const uint4* g = reinterpret_cast<const uint4*>(
                            g_xth + (size_t)(zi * HWs + yi * 64 + x0) * 8);
                        p0 = g[0]; p1 = g[1];
                    }
                    if (okzy && (unsigned)(x0 + 1) < 64u) {
                        const uint4* g = reinterpret_cast<const uint4*>(
                            g_xth + (size_t)(zi * HWs + yi * 64 + x0 + 1) * 8);
                        q0 = g[0]; q1 = g[1];
                    }
#pragma unroll
                    for (int j = 0; j < 4; j++) {
                        __half2 pj = *(reinterpret_cast<__half2*>(&p0) + j);
                        __half2 qj = *(reinterpret_cast<__half2*>(&q0) + j);
                        __half2 tj = __hfma2(qj, wx1h, __hmul2(pj, wx0h));
                        ah[j] = __hfma2(tj, wzyh, ah[j]);
                        __half2 pk2 = *(reinterpret_cast<__half2*>(&p1) + j);
                        __half2 qk2 = *(reinterpret_cast<__half2*>(&q1) + j);
                        __half2 uk = __hfma2(qk2, wx1h, __hmul2(pk2, wx0h));
                        ah[j + 4] = __hfma2(uk, wzyh, ah[j + 4]);
                    }
                }
            }
        }

        // ---- einsum via HMMA: stage ah -> ldmatrix -> mma ----
        __syncwarp();                       // WAR vs previous tap's ldmatrix
        myrow[0] = *reinterpret_cast<uint4*>(&ah[0]);
        myrow[1] = *reinterpret_cast<uint4*>(&ah[4]);
        __syncwarp();                       // RAW
        uint32_t A0[4], A1[4];
        LDM_X4(A0, addrA0);
        LDM_X4(A1, addrA1);
        uint4 b = bfr[k * 32 + lane];
        mma_f16(d,      A0[0], A0[1], A0[2], A0[3], b.x, b.y);
        mma_f16(d + 8,  A1[0], A1[1], A1[2], A1[3], b.x, b.y);
        mma_f16(d + 4,  A0[0], A0[1], A0[2], A0[3], b.z, b.w);
        mma_f16(d + 12, A1[0], A1[1], A1[2], A1[3], b.z, b.w);
    }

    // ---- write out ----
    const int rlo = lane >> 2;
    const int o0  = 2 * (lane & 3);
#pragma unroll
    for (int mt = 0; mt < 2; mt++) {
#pragma unroll
        for (int nt = 0; nt < 2; nt++) {
            const float* dd = d + mt * 8 + nt * 4;
            int vlo = mt * 16 + rlo;
            int vhi = vlo + 8;
            int vox_lo = (bz + (w >> 1)) * HWs
                       + (by + (w & 1) * 4 + (vlo >> 3)) * 64 + bx + (vlo & 7);
            int vox_hi = (bz + (w >> 1)) * HWs
                       + (by + (w & 1) * 4 + (vhi >> 3)) * 64 + bx + (vhi & 7);
            out[(size_t)(nt * 8 + o0    ) * DHW + vox_lo] = dd[0];
            out[(size_t)(nt * 8 + o0 + 1) * DHW + vox_lo] = dd[1];
            out[(size_t)(nt * 8 + o0    ) * DHW + vox_hi] = dd[2];
            out[(size_t)(nt * 8 + o0 + 1) * DHW + vox_hi] = dd[3];
        }
    }
}

// ---------------------------------------------------------------------------
extern "C" void kernel_launch(void* const* d_in, const int* in_sizes, int n_in,
                              void* d_out, int out_size)
{
    const float* x    = (const float*)d_in[0];   // [16,64,64,64]
    const float* kern = (const float*)d_in[1];   // [27,16,16]
    const float* pk   = (const float*)d_in[2];   // [27,16,81]
    float* out = (float*)d_out;                  // [16,64,64,64]

    cudaFuncSetAttribute(k_gemm,   cudaFuncAttributeMaxDynamicSharedMemorySize, 65664);
    cudaFuncSetAttribute(k_deform, cudaFuncAttributeMaxDynamicSharedMemorySize, 74784);

    k_bfragG<<<21, 256>>>(pk);
    k_bfragD<<<4, 256>>>(kern);
    k_transpose<<<1024, 256>>>(x);
    k_gemm<<<dim3(32, 64), 256, 65664>>>(x);
    k_deform<<<dim3(8, 8, 16), 256, 74784>>>(out);
}

// round 10
// speedup vs baseline: 4.3770x; 1.0113x over previous
#include <cuda_runtime.h>
#include <cuda_fp16.h>
#include <cstdint>

#define HWs  4096
#define DHW  262144

// ---------------- scratch (device globals; allocation-free rule) -----------
__device__ __half2 g_xth[(size_t)DHW * 8];    // x channel-last fp16 [v][c]
__device__ uint2   g_offh[(size_t)27 * DHW];  // offsets tap-major fp16 (oz,oy,ox,0)
__device__ uint4   g_BfragG[5184];            // gemm W frags [27][6][32] uint4
__device__ uint4   g_BfragD[864];             // einsum kern frags [27][32] uint4

// ---- helpers ----------------------------------------------------------------
__device__ __forceinline__ uint32_t smem_u32(const void* p) {
    uint32_t a;
    asm("{ .reg .u64 t; cvta.to.shared.u64 t, %1; cvt.u32.u64 %0, t; }" : "=r"(a) : "l"(p));
    return a;
}
__device__ __forceinline__ void mma_f16(float* d, uint32_t a0, uint32_t a1,
                                        uint32_t a2, uint32_t a3,
                                        uint32_t b0, uint32_t b1) {
    asm volatile(
        "mma.sync.aligned.m16n8k16.row.col.f32.f16.f16.f32 "
        "{%0,%1,%2,%3}, {%4,%5,%6,%7}, {%8,%9}, {%0,%1,%2,%3};"
        : "+f"(d[0]), "+f"(d[1]), "+f"(d[2]), "+f"(d[3])
        : "r"(a0), "r"(a1), "r"(a2), "r"(a3), "r"(b0), "r"(b1));
}
#define LDM_X4(r, addr) asm volatile( \
    "ldmatrix.sync.aligned.m8n8.x4.shared.b16 {%0,%1,%2,%3}, [%4];" \
    : "=r"((r)[0]), "=r"((r)[1]), "=r"((r)[2]), "=r"((r)[3]) : "r"(addr))

// ---------------------------------------------------------------------------
// Prep A: gemm W fragments as uint4 = {nt=2np:(r0,r1), nt=2np+1:(r0,r1)}
// ---------------------------------------------------------------------------
__global__ void __launch_bounds__(256) k_bfragG(const float* __restrict__ pk)
{
    int idx = blockIdx.x * 256 + threadIdx.x;     // < 5184
    if (idx >= 5184) return;
    int tap = idx / 192;
    int rem = idx - tap * 192;
    int np  = rem >> 5;
    int l   = rem & 31;
    int c0  = 2 * (l & 3);
    int n0  = 16 * np + (l >> 2);
    int n1  = n0 + 8;
    int kb  = tap * 16;
    float a0 = (n0 < 81) ? pk[(kb + c0    ) * 81 + n0] : 0.f;
    float a1 = (n0 < 81) ? pk[(kb + c0 + 1) * 81 + n0] : 0.f;
    float b0 = (n0 < 81) ? pk[(kb + c0 + 8) * 81 + n0] : 0.f;
    float b1 = (n0 < 81) ? pk[(kb + c0 + 9) * 81 + n0] : 0.f;
    float c2 = (n1 < 81) ? pk[(kb + c0    ) * 81 + n1] : 0.f;
    float c3 = (n1 < 81) ? pk[(kb + c0 + 1) * 81 + n1] : 0.f;
    float d2 = (n1 < 81) ? pk[(kb + c0 + 8) * 81 + n1] : 0.f;
    float d3 = (n1 < 81) ? pk[(kb + c0 + 9) * 81 + n1] : 0.f;
    __half2 h0 = __floats2half2_rn(a0, a1);
    __half2 h1 = __floats2half2_rn(b0, b1);
    __half2 h2 = __floats2half2_rn(c2, c3);
    __half2 h3 = __floats2half2_rn(d2, d3);
    g_BfragG[idx] = make_uint4(*reinterpret_cast<uint32_t*>(&h0),
                               *reinterpret_cast<uint32_t*>(&h1),
                               *reinterpret_cast<uint32_t*>(&h2),
                               *reinterpret_cast<uint32_t*>(&h3));
}

// ---------------------------------------------------------------------------
// Prep B: einsum kern fragments as uint4 {nt0:(lo,hi), nt1:(lo,hi)}
// ---------------------------------------------------------------------------
__global__ void __launch_bounds__(256) k_bfragD(const float* __restrict__ kern)
{
    int idx = blockIdx.x * 256 + threadIdx.x;     // < 864
    if (idx >= 864) return;
    int tap = idx >> 5;
    int l   = idx & 31;
    int c0  = 2 * (l & 3);
    int o0  = l >> 2;
    int kb  = tap * 16;
    __half2 h0 = __floats2half2_rn(kern[(kb + c0    ) * 16 + o0],
                                   kern[(kb + c0 + 1) * 16 + o0]);
    __half2 h1 = __floats2half2_rn(kern[(kb + c0 + 8) * 16 + o0],
                                   kern[(kb + c0 + 9) * 16 + o0]);
    __half2 h2 = __floats2half2_rn(kern[(kb + c0    ) * 16 + o0 + 8],
                                   kern[(kb + c0 + 1) * 16 + o0 + 8]);
    __half2 h3 = __floats2half2_rn(kern[(kb + c0 + 8) * 16 + o0 + 8],
                                   kern[(kb + c0 + 9) * 16 + o0 + 8]);
    g_BfragD[idx] = make_uint4(*reinterpret_cast<uint32_t*>(&h0),
                               *reinterpret_cast<uint32_t*>(&h1),
                               *reinterpret_cast<uint32_t*>(&h2),
                               *reinterpret_cast<uint32_t*>(&h3));
}

// ---------------------------------------------------------------------------
// Kernel 0: transpose x [c][v] -> fp16 channel-last [v][c]
// ---------------------------------------------------------------------------
__global__ void __launch_bounds__(256) k_transpose(const float* __restrict__ x)
{
    int v = blockIdx.x * 256 + threadIdx.x;
    float vals[16];
#pragma unroll
    for (int c = 0; c < 16; c++)
        vals[c] = x[(size_t)c * DHW + v];
    __half2 h[8];
#pragma unroll
    for (int i = 0; i < 8; i++)
        h[i] = __floats2half2_rn(vals[2*i], vals[2*i+1]);
    uint4* dst = reinterpret_cast<uint4*>(g_xth + (size_t)v * 8);
    dst[0] = *reinterpret_cast<uint4*>(&h[0]);
    dst[1] = *reinterpret_cast<uint4*>(&h[4]);
}

// ---------------------------------------------------------------------------
// Kernel 1: offset GEMM. Block = 128 voxels (z fixed, 2 y-rows, 64 x),
// 256 thr / 8 warps; warp = (m-group 0..3) x (N-half 0..1).
// SMEM: B phase buf (9 taps, 27648 B) @0; patch 38016 B @27648;
//       stage (51200 B) reuses @0. Total 65664 B -> 3/SM.
// ---------------------------------------------------------------------------
__global__ void __launch_bounds__(256, 3) k_gemm(const float* __restrict__ x)
{
    extern __shared__ char smem[];
    const uint32_t smem_base = smem_u32(smem);
    uint4* bsm = reinterpret_cast<uint4*>(smem);               // B frags
    uint32_t* patch = reinterpret_cast<uint32_t*>(smem + 27648);
    float* stage = reinterpret_cast<float*>(smem);

    const int t    = threadIdx.x;
    const int lane = t & 31;
    const int w    = t >> 5;
    const int mg    = w >> 1;      // m-group: 32 voxels
    const int nhalf = w & 1;       // N half
    const int z    = blockIdx.y;
    const int y0   = blockIdx.x * 2;

    // x patch fp16: slot = (pz*4+py)*66+px, 8 half2 @ pitch 12 u32 (48 B)
    for (int j = t; j < 6336; j += 256) {
        int pair = j / 792;
        int slot = j - pair * 792;
        int px = slot % 66;
        int q  = slot / 66;
        int py = q & 3, pz = q >> 2;
        int gz = z - 1 + pz, gy = y0 - 1 + py, gx = px - 1;
        float f0 = 0.f, f1 = 0.f;
        if ((unsigned)gz < 64u && (unsigned)gy < 64u && (unsigned)gx < 64u) {
            int g = gz * HWs + gy * 64 + gx;
            f0 = x[(size_t)(2 * pair    ) * DHW + g];
            f1 = x[(size_t)(2 * pair + 1) * DHW + g];
        }
        __half2 h = __floats2half2_rn(f0, f1);
        patch[slot * 12 + pair] = *reinterpret_cast<uint32_t*>(&h);
    }

    // ldmatrix lane address bases (per m-tile)
    const int rowInTile = (lane & 7) + ((lane >> 3) & 1) * 8;
    const int khalf = lane >> 4;
    uint32_t abase[2];
#pragma unroll
    for (int mt = 0; mt < 2; mt++) {
        int r  = mg * 32 + mt * 16 + rowInTile;
        int sy = r >> 6, sx = r & 63;
        abase[mt] = smem_base + 27648u + (uint32_t)((sy * 66 + sx) * 48) + khalf * 16u;
    }

    float d[48];
#pragma unroll
    for (int i = 0; i < 48; i++) d[i] = 0.f;

#pragma unroll 1
    for (int phase = 0; phase < 3; phase++) {
        if (phase) __syncthreads();          // prev-phase B reads done
        for (int i = t; i < 1728; i += 256)
            bsm[i] = g_BfragG[phase * 1728 + i];
        __syncthreads();
#pragma unroll 1
        for (int tl = 0; tl < 9; tl++) {
            const int tap = phase * 9 + tl;
            const int kd = tap / 9, kh = (tap / 3) % 3, kw = tap % 3;
            const uint32_t aoff = (uint32_t)(((kd * 4 + kh) * 66 + kw) * 48);
            uint32_t A0[4], A1[4];
            LDM_X4(A0, abase[0] + aoff);
            LDM_X4(A1, abase[1] + aoff);
            const uint4* bp = bsm + tl * 192 + nhalf * 96 + lane;
#pragma unroll
            for (int np = 0; np < 3; np++) {
                uint4 b = bp[np * 32];
                float* d0 = d + (np * 4    ) * 4;
                float* d1 = d + (np * 4 + 1) * 4;
                float* d2 = d + (np * 4 + 2) * 4;
                float* d3 = d + (np * 4 + 3) * 4;
                mma_f16(d0, A0[0], A0[1], A0[2], A0[3], b.x, b.y);
                mma_f16(d1, A1[0], A1[1], A1[2], A1[3], b.x, b.y);
                mma_f16(d2, A0[0], A0[1], A0[2], A0[3], b.z, b.w);
                mma_f16(d3, A1[0], A1[1], A1[2], A1[3], b.z, b.w);
            }
        }
    }
    __syncthreads();   // B + patch dead; reuse as stage

    // stage D: [128 vox][pitch 100]
    const int rlo  = lane >> 2;
    const int col0 = 2 * (lane & 3);
#pragma unroll
    for (int mt = 0; mt < 2; mt++) {
#pragma unroll
        for (int np = 0; np < 3; np++) {
#pragma unroll
            for (int ntl = 0; ntl < 2; ntl++) {
                const float* dd = d + ((np * 2 + ntl) * 2 + mt) * 4;
                int lr0 = mg * 32 + mt * 16 + rlo;
                int col = (2 * (nhalf * 3 + np) + ntl) * 8 + col0;
                stage[lr0 * 100 + col    ] = dd[0];
                stage[lr0 * 100 + col + 1] = dd[1];
                stage[(lr0 + 8) * 100 + col    ] = dd[2];
                stage[(lr0 + 8) * 100 + col + 1] = dd[3];
            }
        }
    }
    __syncthreads();

    // coalesced tap-major fp16 offset writes
    for (int i = t; i < 3456; i += 256) {
        int tap = i >> 7;
        int v   = i & 127;
        int vox = z * HWs + (y0 + (v >> 6)) * 64 + (v & 63);
        const float* s = stage + v * 100 + 3 * tap;
        __half2 h0 = __floats2half2_rn(s[0], s[1]);
        __half2 h1 = __floats2half2_rn(s[2], 0.f);
        g_offh[(size_t)tap * DHW + vox] =
            make_uint2(*reinterpret_cast<uint32_t*>(&h0),
                       *reinterpret_cast<uint32_t*>(&h1));
    }
}

// ---------------------------------------------------------------------------
// Kernel 2: deformable gather (half2 interp) + HMMA einsum.
// Block: 8x8x8 = 512 voxels, 16 warps. SMEM: region [13][13][13][16ch fp16]
// 70304 B @0; kern frags 13824 B @70304; A stage 24576 B @84128 = 108704 B
// -> 2 blocks/SM (32 warps, 50% occ).
// ---------------------------------------------------------------------------
__global__ void __launch_bounds__(512, 2) k_deform(float* __restrict__ out)
{
    extern __shared__ char smem[];
    __half2* xrh = reinterpret_cast<__half2*>(smem);
    const uint4* bfr = reinterpret_cast<const uint4*>(smem + 70304);
    const uint32_t smem_base = smem_u32(smem);

    const int t    = threadIdx.x;
    const int lane = t & 31;
    const int w    = t >> 5;

    // kern fragments -> smem (864 uint4)
    {
        uint4* bd = reinterpret_cast<uint4*>(smem + 70304);
        for (int i = t; i < 864; i += 512) bd[i] = g_BfragD[i];
    }

    const int bz = blockIdx.z * 8, by = blockIdx.y * 8, bx = blockIdx.x * 8;
    const int roz = bz - 2, roy = by - 2, rox = bx - 2;

    // region: 13*13*13 = 2197 points x 32 B
    {
        const uint4* xthq = reinterpret_cast<const uint4*>(g_xth);
        uint4* xrq = reinterpret_cast<uint4*>(smem);
        for (int u = t; u < 4394; u += 512) {
            int q = u & 1;
            int p = u >> 1;
            int rx = p % 13;
            int p2 = p / 13;
            int ry = p2 % 13;
            int rz = p2 / 13;
            int gz = roz + rz, gy = roy + ry, gx = rox + rx;
            uint4 v = make_uint4(0u, 0u, 0u, 0u);
            if ((unsigned)gz < 64u && (unsigned)gy < 64u && (unsigned)gx < 64u)
                v = xthq[(size_t)(gz * HWs + gy * 64 + gx) * 2 + q];
            xrq[p * 2 + q] = v;
        }
    }
    __syncthreads();

    const int lx = t & 7, ly = (t >> 3) & 7, lz = t >> 6;   // lz 0..7
    const int pz = bz + lz, py = by + ly, px = bx + lx;
    const int vox = pz * HWs + py * 64 + px;
    const uint2* offp = g_offh + vox;

    // A-stage pointers (per-warp, row = lane, pitch 48 B)
    const uint32_t asb = 84128u + (uint32_t)w * 1536u;
    uint4* myrow = reinterpret_cast<uint4*>(smem + asb + lane * 48);
    const uint32_t addrA0 = smem_base + asb + (uint32_t)(lane & 15) * 48u
                          + (uint32_t)(lane >> 4) * 16u;
    const uint32_t addrA1 = addrA0 + 768u;

    float d[16];
#pragma unroll
    for (int q = 0; q < 16; q++) d[q] = 0.f;

#pragma unroll 1
    for (int k = 0; k < 27; k++) {
        const int kd = k / 9;
        const int kh = (k - kd * 9) / 3;
        const int kw = k - kd * 9 - kh * 3;

        uint2 ob = offp[(size_t)k * DHW];
        float2 ozy = __half22float2(*reinterpret_cast<__half2*>(&ob.x));
        float2 oxp = __half22float2(*reinterpret_cast<__half2*>(&ob.y));
        float cz = (float)(pz + kd - 1) + ozy.x;
        float cy = (float)(py + kh - 1) + ozy.y;
        float cx = (float)(px + kw - 1) + oxp.x;

        float z0f = floorf(cz), y0f = floorf(cy), x0f = floorf(cx);
        float fz = cz - z0f, fy = cy - y0f, fx = cx - x0f;
        int z0 = (int)z0f, y0 = (int)y0f, x0 = (int)x0f;
        int lz0 = z0 - roz, ly0 = y0 - roy, lx0 = x0 - rox;

        const __half2 wx0h = __float2half2_rn(1.f - fx);
        const __half2 wx1h = __float2half2_rn(fx);

        __half2 ah[8];
#pragma unroll
        for (int j = 0; j < 8; j++) ah[j] = __float2half2_rn(0.f);

        if ((unsigned)lz0 <= 11u && (unsigned)ly0 <= 11u && (unsigned)lx0 <= 11u) {
            // fast path: both x-corners inside region (zero-padded OOB)
#pragma unroll
            for (int dz = 0; dz < 2; dz++) {
                float wz = dz ? fz : 1.f - fz;
#pragma unroll
                for (int dy = 0; dy < 2; dy++) {
                    __half2 wzyh = __float2half2_rn(wz * (dy ? fy : 1.f - fy));
                    const __half2* hp = xrh +
                        ((lz0 + dz) * 169 + (ly0 + dy) * 13 + lx0) * 8;
                    uint4 p0 = *reinterpret_cast<const uint4*>(hp);
                    uint4 p1 = *reinterpret_cast<const uint4*>(hp + 4);
                    uint4 q0 = *reinterpret_cast<const uint4*>(hp + 8);
                    uint4 q1 = *reinterpret_cast<const uint4*>(hp + 12);
#pragma unroll
                    for (int j = 0; j < 4; j++) {
                        __half2 pj = *(reinterpret_cast<__half2*>(&p0) + j);
                        __half2 qj = *(reinterpret_cast<__half2*>(&q0) + j);
                        __half2 tj = __hfma2(qj, wx1h, __hmul2(pj, wx0h));
                        ah[j] = __hfma2(tj, wzyh, ah[j]);
                        __half2 pk2 = *(reinterpret_cast<__half2*>(&p1) + j);
                        __half2 qk2 = *(reinterpret_cast<__half2*>(&q1) + j);
                        __half2 uk = __hfma2(qk2, wx1h, __hmul2(pk2, wx0h));
                        ah[j + 4] = __hfma2(uk, wzyh, ah[j + 4]);
                    }
                }
            }
        } else {
            // exact fallback: per-corner validity, global fp16 reads
#pragma unroll
            for (int dz = 0; dz < 2; dz++) {
                float wz = dz ? fz : 1.f - fz;
#pragma unroll
                for (int dy = 0; dy < 2; dy++) {
                    __half2 wzyh = __float2half2_rn(wz * (dy ? fy : 1.f - fy));
                    int zi = z0 + dz, yi = y0 + dy;
                    bool okzy = ((unsigned)zi < 64u) && ((unsigned)yi < 64u);
                    uint4 p0 = make_uint4(0,0,0,0), p1 = p0, q0 = p0, q1 = p0;
                    if (okzy && (unsigned)x0 < 64u) {
                        const uint4* g = reinterpret_cast<const uint4*>(
                            g_xth + (size_t)(zi * HWs + yi * 64 + x0) * 8);
                        p0 = g[0]; p1 = g[1];
                    }
                    if (okzy && (unsigned)(x0 + 1) < 64u) {
                        const uint4* g = reinterpret_cast<const uint4*>(
                            g_xth + (size_t)(zi * HWs + yi * 64 + x0 + 1) * 8);
                        q0 = g[0]; q1 = g[1];
                    }
#pragma unroll
                    for (int j = 0; j < 4; j++) {
                        __half2 pj = *(reinterpret_cast<__half2*>(&p0) + j);
                        __half2 qj = *(reinterpret_cast<__half2*>(&q0) + j);
                        __half2 tj = __hfma2(qj, wx1h, __hmul2(pj, wx0h));
                        ah[j] = __hfma2(tj, wzyh, ah[j]);
                        __half2 pk2 = *(reinterpret_cast<__half2*>(&p1) + j);
                        __half2 qk2 = *(reinterpret_cast<__half2*>(&q1) + j);
                        __half2 uk = __hfma2(qk2, wx1h, __hmul2(pk2, wx0h));
                        ah[j + 4] = __hfma2(uk, wzyh, ah[j + 4]);
                    }
                }
            }
        }

        // ---- einsum via HMMA: stage ah -> ldmatrix -> mma ----
        __syncwarp();                       // WAR vs previous tap's ldmatrix
        myrow[0] = *reinterpret_cast<uint4*>(&ah[0]);
        myrow[1] = *reinterpret_cast<uint4*>(&ah[4]);
        __syncwarp();                       // RAW
        uint32_t A0[4], A1[4];
        LDM_X4(A0, addrA0);
        LDM_X4(A1, addrA1);
        uint4 b = bfr[k * 32 + lane];
        mma_f16(d,      A0[0], A0[1], A0[2], A0[3], b.x, b.y);
        mma_f16(d + 8,  A1[0], A1[1], A1[2], A1[3], b.x, b.y);
        mma_f16(d + 4,  A0[0], A0[1], A0[2], A0[3], b.z, b.w);
        mma_f16(d + 12, A1[0], A1[1], A1[2], A1[3], b.z, b.w);
    }

    // ---- write out ----
    const int rlo = lane >> 2;
    const int o0  = 2 * (lane & 3);
#pragma unroll
    for (int mt = 0; mt < 2; mt++) {
#pragma unroll
        for (int nt = 0; nt < 2; nt++) {
            const float* dd = d + mt * 8 + nt * 4;
            int vlo = mt * 16 + rlo;
            int vhi = vlo + 8;
            int vox_lo = (bz + (w >> 1)) * HWs
                       + (by + (w & 1) * 4 + (vlo >> 3)) * 64 + bx + (vlo & 7);
            int vox_hi = (bz + (w >> 1)) * HWs
                       + (by + (w & 1) * 4 + (vhi >> 3)) * 64 + bx + (vhi & 7);
            out[(size_t)(nt * 8 + o0    ) * DHW + vox_lo] = dd[0];
            out[(size_t)(nt * 8 + o0 + 1) * DHW + vox_lo] = dd[1];
            out[(size_t)(nt * 8 + o0    ) * DHW + vox_hi] = dd[2];
            out[(size_t)(nt * 8 + o0 + 1) * DHW + vox_hi] = dd[3];
        }
    }
}

// ---------------------------------------------------------------------------
extern "C" void kernel_launch(void* const* d_in, const int* in_sizes, int n_in,
                              void* d_out, int out_size)
{
    const float* x    = (const float*)d_in[0];   // [16,64,64,64]
    const float* kern = (const float*)d_in[1];   // [27,16,16]
    const float* pk   = (const float*)d_in[2];   // [27,16,81]
    float* out = (float*)d_out;                  // [16,64,64,64]

    cudaFuncSetAttribute(k_gemm,   cudaFuncAttributeMaxDynamicSharedMemorySize, 65664);
    cudaFuncSetAttribute(k_deform, cudaFuncAttributeMaxDynamicSharedMemorySize, 108704);

    k_bfragG<<<21, 256>>>(pk);
    k_bfragD<<<4, 256>>>(kern);
    k_transpose<<<1024, 256>>>(x);
    k_gemm<<<dim3(32, 64), 256, 65664>>>(x);
    k_deform<<<dim3(8, 8, 8), 512, 108704>>>(out);
}

// round 11
// speedup vs baseline: 5.3872x; 1.2308x over previous
#include <cuda_runtime.h>
#include <cuda_fp16.h>
#include <cstdint>

#define HWs  4096
#define DHW  262144

// ---------------- scratch (device globals; allocation-free rule) -----------
__device__ __half2 g_xth[(size_t)DHW * 8];    // x channel-last fp16 [v][c]
__device__ uint2   g_offh[(size_t)27 * DHW];  // offsets tap-major fp16 (oz,oy,ox,0)
__device__ uint4   g_BfragG[5184];            // gemm W frags [27][6][32] uint4
__device__ uint4   g_BfragD[864];             // einsum kern frags [27][32] uint4

// ---- helpers ----------------------------------------------------------------
__device__ __forceinline__ uint32_t smem_u32(const void* p) {
    uint32_t a;
    asm("{ .reg .u64 t; cvta.to.shared.u64 t, %1; cvt.u32.u64 %0, t; }" : "=r"(a) : "l"(p));
    return a;
}
__device__ __forceinline__ void mma_f16(float* d, uint32_t a0, uint32_t a1,
                                        uint32_t a2, uint32_t a3,
                                        uint32_t b0, uint32_t b1) {
    asm volatile(
        "mma.sync.aligned.m16n8k16.row.col.f32.f16.f16.f32 "
        "{%0,%1,%2,%3}, {%4,%5,%6,%7}, {%8,%9}, {%0,%1,%2,%3};"
        : "+f"(d[0]), "+f"(d[1]), "+f"(d[2]), "+f"(d[3])
        : "r"(a0), "r"(a1), "r"(a2), "r"(a3), "r"(b0), "r"(b1));
}
#define LDM_X4(r, addr) asm volatile( \
    "ldmatrix.sync.aligned.m8n8.x4.shared.b16 {%0,%1,%2,%3}, [%4];" \
    : "=r"((r)[0]), "=r"((r)[1]), "=r"((r)[2]), "=r"((r)[3]) : "r"(addr))

// ---------------------------------------------------------------------------
// Prep A: gemm W fragments as uint4 = {nt=2np:(r0,r1), nt=2np+1:(r0,r1)}
// ---------------------------------------------------------------------------
__global__ void __launch_bounds__(256) k_bfragG(const float* __restrict__ pk)
{
    int idx = blockIdx.x * 256 + threadIdx.x;     // < 5184
    if (idx >= 5184) return;
    int tap = idx / 192;
    int rem = idx - tap * 192;
    int np  = rem >> 5;
    int l   = rem & 31;
    int c0  = 2 * (l & 3);
    int n0  = 16 * np + (l >> 2);
    int n1  = n0 + 8;
    int kb  = tap * 16;
    float a0 = (n0 < 81) ? pk[(kb + c0    ) * 81 + n0] : 0.f;
    float a1 = (n0 < 81) ? pk[(kb + c0 + 1) * 81 + n0] : 0.f;
    float b0 = (n0 < 81) ? pk[(kb + c0 + 8) * 81 + n0] : 0.f;
    float b1 = (n0 < 81) ? pk[(kb + c0 + 9) * 81 + n0] : 0.f;
    float c2 = (n1 < 81) ? pk[(kb + c0    ) * 81 + n1] : 0.f;
    float c3 = (n1 < 81) ? pk[(kb + c0 + 1) * 81 + n1] : 0.f;
    float d2 = (n1 < 81) ? pk[(kb + c0 + 8) * 81 + n1] : 0.f;
    float d3 = (n1 < 81) ? pk[(kb + c0 + 9) * 81 + n1] : 0.f;
    __half2 h0 = __floats2half2_rn(a0, a1);
    __half2 h1 = __floats2half2_rn(b0, b1);
    __half2 h2 = __floats2half2_rn(c2, c3);
    __half2 h3 = __floats2half2_rn(d2, d3);
    g_BfragG[idx] = make_uint4(*reinterpret_cast<uint32_t*>(&h0),
                               *reinterpret_cast<uint32_t*>(&h1),
                               *reinterpret_cast<uint32_t*>(&h2),
                               *reinterpret_cast<uint32_t*>(&h3));
}

// ---------------------------------------------------------------------------
// Prep B: einsum kern fragments as uint4 {nt0:(lo,hi), nt1:(lo,hi)}
// ---------------------------------------------------------------------------
__global__ void __launch_bounds__(256) k_bfragD(const float* __restrict__ kern)
{
    int idx = blockIdx.x * 256 + threadIdx.x;     // < 864
    if (idx >= 864) return;
    int tap = idx >> 5;
    int l   = idx & 31;
    int c0  = 2 * (l & 3);
    int o0  = l >> 2;
    int kb  = tap * 16;
    __half2 h0 = __floats2half2_rn(kern[(kb + c0    ) * 16 + o0],
                                   kern[(kb + c0 + 1) * 16 + o0]);
    __half2 h1 = __floats2half2_rn(kern[(kb + c0 + 8) * 16 + o0],
                                   kern[(kb + c0 + 9) * 16 + o0]);
    __half2 h2 = __floats2half2_rn(kern[(kb + c0    ) * 16 + o0 + 8],
                                   kern[(kb + c0 + 1) * 16 + o0 + 8]);
    __half2 h3 = __floats2half2_rn(kern[(kb + c0 + 8) * 16 + o0 + 8],
                                   kern[(kb + c0 + 9) * 16 + o0 + 8]);
    g_BfragD[idx] = make_uint4(*reinterpret_cast<uint32_t*>(&h0),
                               *reinterpret_cast<uint32_t*>(&h1),
                               *reinterpret_cast<uint32_t*>(&h2),
                               *reinterpret_cast<uint32_t*>(&h3));
}

// ---------------------------------------------------------------------------
// Kernel 0: transpose x [c][v] -> fp16 channel-last [v][c]
// ---------------------------------------------------------------------------
__global__ void __launch_bounds__(256) k_transpose(const float* __restrict__ x)
{
    int v = blockIdx.x * 256 + threadIdx.x;
    float vals[16];
#pragma unroll
    for (int c = 0; c < 16; c++)
        vals[c] = x[(size_t)c * DHW + v];
    __half2 h[8];
#pragma unroll
    for (int i = 0; i < 8; i++)
        h[i] = __floats2half2_rn(vals[2*i], vals[2*i+1]);
    uint4* dst = reinterpret_cast<uint4*>(g_xth + (size_t)v * 8);
    dst[0] = *reinterpret_cast<uint4*>(&h[0]);
    dst[1] = *reinterpret_cast<uint4*>(&h[4]);
}

// ---------------------------------------------------------------------------
// Kernel 1: offset GEMM. Block = 128 voxels (z fixed, 2 y-rows, 64 x),
// 256 thr / 8 warps; warp = (m-group 0..3) x (N-half 0..1).
// SMEM: B phase buf (9 taps, 27648 B) @0; patch 38016 B @27648;
//       stage (51200 B) reuses @0. Total 65664 B -> 3/SM.
// ---------------------------------------------------------------------------
__global__ void __launch_bounds__(256, 3) k_gemm(const float* __restrict__ x)
{
    extern __shared__ char smem[];
    const uint32_t smem_base = smem_u32(smem);
    uint4* bsm = reinterpret_cast<uint4*>(smem);               // B frags
    uint32_t* patch = reinterpret_cast<uint32_t*>(smem + 27648);
    float* stage = reinterpret_cast<float*>(smem);

    const int t    = threadIdx.x;
    const int lane = t & 31;
    const int w    = t >> 5;
    const int mg    = w >> 1;      // m-group: 32 voxels
    const int nhalf = w & 1;       // N half
    const int z    = blockIdx.y;
    const int y0   = blockIdx.x * 2;

    // x patch fp16: slot = (pz*4+py)*66+px, 8 half2 @ pitch 12 u32 (48 B)
    for (int j = t; j < 6336; j += 256) {
        int pair = j / 792;
        int slot = j - pair * 792;
        int px = slot % 66;
        int q  = slot / 66;
        int py = q & 3, pz = q >> 2;
        int gz = z - 1 + pz, gy = y0 - 1 + py, gx = px - 1;
        float f0 = 0.f, f1 = 0.f;
        if ((unsigned)gz < 64u && (unsigned)gy < 64u && (unsigned)gx < 64u) {
            int g = gz * HWs + gy * 64 + gx;
            f0 = x[(size_t)(2 * pair    ) * DHW + g];
            f1 = x[(size_t)(2 * pair + 1) * DHW + g];
        }
        __half2 h = __floats2half2_rn(f0, f1);
        patch[slot * 12 + pair] = *reinterpret_cast<uint32_t*>(&h);
    }

    // ldmatrix lane address bases (per m-tile)
    const int rowInTile = (lane & 7) + ((lane >> 3) & 1) * 8;
    const int khalf = lane >> 4;
    uint32_t abase[2];
#pragma unroll
    for (int mt = 0; mt < 2; mt++) {
        int r  = mg * 32 + mt * 16 + rowInTile;
        int sy = r >> 6, sx = r & 63;
        abase[mt] = smem_base + 27648u + (uint32_t)((sy * 66 + sx) * 48) + khalf * 16u;
    }

    float d[48];
#pragma unroll
    for (int i = 0; i < 48; i++) d[i] = 0.f;

#pragma unroll 1
    for (int phase = 0; phase < 3; phase++) {
        if (phase) __syncthreads();          // prev-phase B reads done
        for (int i = t; i < 1728; i += 256)
            bsm[i] = g_BfragG[phase * 1728 + i];
        __syncthreads();
#pragma unroll
        for (int tl = 0; tl < 9; tl++) {     // fully unrolled: aoff const-folded
            const int kh = tl / 3, kw = tl % 3;     // kd == phase
            const uint32_t aoff = (uint32_t)(((kh) * 66 + kw) * 48);
            uint32_t A0[4], A1[4];
            LDM_X4(A0, abase[0] + aoff);
            LDM_X4(A1, abase[1] + aoff);
            const uint4* bp = bsm + tl * 192 + nhalf * 96 + lane;
#pragma unroll
            for (int np = 0; np < 3; np++) {
                uint4 b = bp[np * 32];
                float* d0 = d + (np * 4    ) * 4;
                float* d1 = d + (np * 4 + 1) * 4;
                float* d2 = d + (np * 4 + 2) * 4;
                float* d3 = d + (np * 4 + 3) * 4;
                mma_f16(d0, A0[0], A0[1], A0[2], A0[3], b.x, b.y);
                mma_f16(d1, A1[0], A1[1], A1[2], A1[3], b.x, b.y);
                mma_f16(d2, A0[0], A0[1], A0[2], A0[3], b.z, b.w);
                mma_f16(d3, A1[0], A1[1], A1[2], A1[3], b.z, b.w);
            }
        }
        // advance A base by one z-plane of the patch (kd = phase)
        abase[0] += (uint32_t)(4 * 66 * 48);
        abase[1] += (uint32_t)(4 * 66 * 48);
    }
    __syncthreads();   // B + patch dead; reuse as stage

    // stage D: [128 vox][pitch 100]
    const int rlo  = lane >> 2;
    const int col0 = 2 * (lane & 3);
#pragma unroll
    for (int mt = 0; mt < 2; mt++) {
#pragma unroll
        for (int np = 0; np < 3; np++) {
#pragma unroll
            for (int ntl = 0; ntl < 2; ntl++) {
                const float* dd = d + ((np * 2 + ntl) * 2 + mt) * 4;
                int lr0 = mg * 32 + mt * 16 + rlo;
                int col = (2 * (nhalf * 3 + np) + ntl) * 8 + col0;
                stage[lr0 * 100 + col    ] = dd[0];
                stage[lr0 * 100 + col + 1] = dd[1];
                stage[(lr0 + 8) * 100 + col    ] = dd[2];
                stage[(lr0 + 8) * 100 + col + 1] = dd[3];
            }
        }
    }
    __syncthreads();

    // coalesced tap-major fp16 offset writes
    for (int i = t; i < 3456; i += 256) {
        int tap = i >> 7;
        int v   = i & 127;
        int vox = z * HWs + (y0 + (v >> 6)) * 64 + (v & 63);
        const float* s = stage + v * 100 + 3 * tap;
        __half2 h0 = __floats2half2_rn(s[0], s[1]);
        __half2 h1 = __floats2half2_rn(s[2], 0.f);
        g_offh[(size_t)tap * DHW + vox] =
            make_uint2(*reinterpret_cast<uint32_t*>(&h0),
                       *reinterpret_cast<uint32_t*>(&h1));
    }
}

// ---------------------------------------------------------------------------
// Kernel 2: deformable gather (half2 interp, split-plane region) + HMMA einsum.
// Block: 8x8x8 = 512 voxels, 16 warps.
// SMEM: region 2 planes x [13][13][13] points x 16 B (ch 0-7 / 8-15),
//       70304 B @0; kern frags 13824 B @70304; A stage 24576 B @84128
//       = 108704 B -> 2 blocks/SM.
// Split planes make every gather LDS.128 lane-dense (16 B point stride):
// 4 wavefronts/instr instead of 8.
// ---------------------------------------------------------------------------
__global__ void __launch_bounds__(512, 2) k_deform(float* __restrict__ out)
{
    extern __shared__ char smem[];
    const uint4* xrq = reinterpret_cast<const uint4*>(smem);   // 2 x 2197 uint4
    const uint4* bfr = reinterpret_cast<const uint4*>(smem + 70304);
    const uint32_t smem_base = smem_u32(smem);

    const int t    = threadIdx.x;
    const int lane = t & 31;
    const int w    = t >> 5;

    // kern fragments -> smem (864 uint4)
    {
        uint4* bd = reinterpret_cast<uint4*>(smem + 70304);
        for (int i = t; i < 864; i += 512) bd[i] = g_BfragD[i];
    }

    const int bz = blockIdx.z * 8, by = blockIdx.y * 8, bx = blockIdx.x * 8;
    const int roz = bz - 2, roy = by - 2, rox = bx - 2;

    // region: 2197 points x 2 planes (ch0-7, ch8-15), 16 B each
    {
        const uint4* xthq = reinterpret_cast<const uint4*>(g_xth);
        uint4* xw = reinterpret_cast<uint4*>(smem);
        for (int u = t; u < 4394; u += 512) {
            int q = u & 1;      // plane
            int p = u >> 1;     // point
            int rx = p % 13;
            int p2 = p / 13;
            int ry = p2 % 13;
            int rz = p2 / 13;
            int gz = roz + rz, gy = roy + ry, gx = rox + rx;
            uint4 v = make_uint4(0u, 0u, 0u, 0u);
            if ((unsigned)gz < 64u && (unsigned)gy < 64u && (unsigned)gx < 64u)
                v = xthq[(size_t)(gz * HWs + gy * 64 + gx) * 2 + q];
            xw[q * 2197 + p] = v;
        }
    }
    __syncthreads();

    const int lx = t & 7, ly = (t >> 3) & 7, lz = t >> 6;   // lz 0..7
    const int pz = bz + lz, py = by + ly, px = bx + lx;
    const int vox = pz * HWs + py * 64 + px;
    const uint2* offp = g_offh + vox;

    // A-stage pointers (per-warp, row = lane, pitch 48 B)
    const uint32_t asb = 84128u + (uint32_t)w * 1536u;
    uint4* myrow = reinterpret_cast<uint4*>(smem + asb + lane * 48);
    const uint32_t addrA0 = smem_base + asb + (uint32_t)(lane & 15) * 48u
                          + (uint32_t)(lane >> 4) * 16u;
    const uint32_t addrA1 = addrA0 + 768u;

    float d[16];
#pragma unroll
    for (int q = 0; q < 16; q++) d[q] = 0.f;

#pragma unroll 1
    for (int k = 0; k < 27; k++) {
        const int kd = k / 9;
        const int kh = (k - kd * 9) / 3;
        const int kw = k - kd * 9 - kh * 3;

        uint2 ob = offp[(size_t)k * DHW];
        float2 ozy = __half22float2(*reinterpret_cast<__half2*>(&ob.x));
        float2 oxp = __half22float2(*reinterpret_cast<__half2*>(&ob.y));
        float cz = (float)(pz + kd - 1) + ozy.x;
        float cy = (float)(py + kh - 1) + ozy.y;
        float cx = (float)(px + kw - 1) + oxp.x;

        float z0f = floorf(cz), y0f = floorf(cy), x0f = floorf(cx);
        float fz = cz - z0f, fy = cy - y0f, fx = cx - x0f;
        int z0 = (int)z0f, y0 = (int)y0f, x0 = (int)x0f;
        int lz0 = z0 - roz, ly0 = y0 - roy, lx0 = x0 - rox;

        const __half2 wx0h = __float2half2_rn(1.f - fx);
        const __half2 wx1h = __float2half2_rn(fx);

        __half2 ah[8];
#pragma unroll
        for (int j = 0; j < 8; j++) ah[j] = __float2half2_rn(0.f);

        if ((unsigned)lz0 <= 11u && (unsigned)ly0 <= 11u && (unsigned)lx0 <= 11u) {
            // fast path: both x-corners inside region (zero-padded OOB)
#pragma unroll
            for (int dz = 0; dz < 2; dz++) {
                float wz = dz ? fz : 1.f - fz;
#pragma unroll
                for (int dy = 0; dy < 2; dy++) {
                    __half2 wzyh = __float2half2_rn(wz * (dy ? fy : 1.f - fy));
                    const int pt = (lz0 + dz) * 169 + (ly0 + dy) * 13 + lx0;
                    uint4 p0 = xrq[pt];            // ch0-7  @x0
                    uint4 q0 = xrq[pt + 1];        // ch0-7  @x1
                    uint4 p1 = xrq[2197 + pt];     // ch8-15 @x0
                    uint4 q1 = xrq[2197 + pt + 1]; // ch8-15 @x1
#pragma unroll
                    for (int j = 0; j < 4; j++) {
                        __half2 pj = *(reinterpret_cast<__half2*>(&p0) + j);
                        __half2 qj = *(reinterpret_cast<__half2*>(&q0) + j);
                        __half2 tj = __hfma2(qj, wx1h, __hmul2(pj, wx0h));
                        ah[j] = __hfma2(tj, wzyh, ah[j]);
                        __half2 pk2 = *(reinterpret_cast<__half2*>(&p1) + j);
                        __half2 qk2 = *(reinterpret_cast<__half2*>(&q1) + j);
                        __half2 uk = __hfma2(qk2, wx1h, __hmul2(pk2, wx0h));
                        ah[j + 4] = __hfma2(uk, wzyh, ah[j + 4]);
                    }
                }
            }
        } else {
            // exact fallback: per-corner validity, global fp16 reads
#pragma unroll
            for (int dz = 0; dz < 2; dz++) {
                float wz = dz ? fz : 1.f - fz;
#pragma unroll
                for (int dy = 0; dy < 2; dy++) {
                    __half2 wzyh = __float2half2_rn(wz * (dy ? fy : 1.f - fy));
                    int zi = z0 + dz, yi = y0 + dy;
                    bool okzy = ((unsigned)zi < 64u) && ((unsigned)yi < 64u);
                    uint4 p0 = make_uint4(0,0,0,0), p1 = p0, q0 = p0, q1 = p0;
                    if (okzy && (unsigned)x0 < 64u) {
                        const uint4* g = reinterpret_cast<const uint4*>(
                            g_xth + (size_t)(zi * HWs + yi * 64 + x0) * 8);
                        p0 = g[0]; p1 = g[1];
                    }
                    if (okzy && (unsigned)(x0 + 1) < 64u) {
                        const uint4* g = reinterpret_cast<const uint4*>(
                            g_xth + (size_t)(zi * HWs + yi * 64 + x0 + 1) * 8);
                        q0 = g[0]; q1 = g[1];
                    }
#pragma unroll
                    for (int j = 0; j < 4; j++) {
                        __half2 pj = *(reinterpret_cast<__half2*>(&p0) + j);
                        __half2 qj = *(reinterpret_cast<__half2*>(&q0) + j);
                        __half2 tj = __hfma2(qj, wx1h, __hmul2(pj, wx0h));
                        ah[j] = __hfma2(tj, wzyh, ah[j]);
                        __half2 pk2 = *(reinterpret_cast<__half2*>(&p1) + j);
                        __half2 qk2 = *(reinterpret_cast<__half2*>(&q1) + j);
                        __half2 uk = __hfma2(qk2, wx1h, __hmul2(pk2, wx0h));
                        ah[j + 4] = __hfma2(uk, wzyh, ah[j + 4]);
                    }
                }
            }
        }

        // ---- einsum via HMMA: stage ah -> ldmatrix -> mma ----
        __syncwarp();                       // WAR vs previous tap's ldmatrix
        myrow[0] = *reinterpret_cast<uint4*>(&ah[0]);
        myrow[1] = *reinterpret_cast<uint4*>(&ah[4]);
        __syncwarp();                       // RAW
        uint32_t A0[4], A1[4];
        LDM_X4(A0, addrA0);
        LDM_X4(A1, addrA1);
        uint4 b = bfr[k * 32 + lane];
        mma_f16(d,      A0[0], A0[1], A0[2], A0[3], b.x, b.y);
        mma_f16(d + 8,  A1[0], A1[1], A1[2], A1[3], b.x, b.y);
        mma_f16(d + 4,  A0[0], A0[1], A0[2], A0[3], b.z, b.w);
        mma_f16(d + 12, A1[0], A1[1], A1[2], A1[3], b.z, b.w);
    }

    // ---- write out ----
    const int rlo = lane >> 2;
    const int o0  = 2 * (lane & 3);
#pragma unroll
    for (int mt = 0; mt < 2; mt++) {
#pragma unroll
        for (int nt = 0; nt < 2; nt++) {
            const float* dd = d + mt * 8 + nt * 4;
            int vlo = mt * 16 + rlo;
            int vhi = vlo + 8;
            int vox_lo = (bz + (w >> 1)) * HWs
                       + (by + (w & 1) * 4 + (vlo >> 3)) * 64 + bx + (vlo & 7);
            int vox_hi = (bz + (w >> 1)) * HWs
                       + (by + (w & 1) * 4 + (vhi >> 3)) * 64 + bx + (vhi & 7);
            out[(size_t)(nt * 8 + o0    ) * DHW + vox_lo] = dd[0];
            out[(size_t)(nt * 8 + o0 + 1) * DHW + vox_lo] = dd[1];
            out[(size_t)(nt * 8 + o0    ) * DHW + vox_hi] = dd[2];
            out[(size_t)(nt * 8 + o0 + 1) * DHW + vox_hi] = dd[3];
        }
    }
}

// ---------------------------------------------------------------------------
extern "C" void kernel_launch(void* const* d_in, const int* in_sizes, int n_in,
                              void* d_out, int out_size)
{
    const float* x    = (const float*)d_in[0];   // [16,64,64,64]
    const float* kern = (const float*)d_in[1];   // [27,16,16]
    const float* pk   = (const float*)d_in[2];   // [27,16,81]
    float* out = (float*)d_out;                  // [16,64,64,64]

    cudaFuncSetAttribute(k_gemm,   cudaFuncAttributeMaxDynamicSharedMemorySize, 65664);
    cudaFuncSetAttribute(k_deform, cudaFuncAttributeMaxDynamicSharedMemorySize, 108704);

    k_bfragG<<<21, 256>>>(pk);
    k_bfragD<<<4, 256>>>(kern);
    k_transpose<<<1024, 256>>>(x);
    k_gemm<<<dim3(32, 64), 256, 65664>>>(x);
    k_deform<<<dim3(8, 8, 8), 512, 108704>>>(out);
}

// round 12
// speedup vs baseline: 5.5730x; 1.0345x over previous
#include <cuda_runtime.h>
#include <cuda_fp16.h>
#include <cstdint>

#define HWs  4096
#define DHW  262144

// ---------------- scratch (device globals; allocation-free rule) -----------
__device__ __half2 g_xth[(size_t)DHW * 8];    // x channel-last fp16 [v][c]
__device__ uint2   g_offh[(size_t)27 * DHW];  // offsets tap-major fp16 (oz,oy,ox,0)
__device__ uint4   g_BfragG[5184];            // gemm W frags [27][6][32] uint4
__device__ uint4   g_BfragD[864];             // einsum kern frags [27][32] uint4

// ---- helpers ----------------------------------------------------------------
__device__ __forceinline__ uint32_t smem_u32(const void* p) {
    uint32_t a;
    asm("{ .reg .u64 t; cvta.to.shared.u64 t, %1; cvt.u32.u64 %0, t; }" : "=r"(a) : "l"(p));
    return a;
}
__device__ __forceinline__ void mma_f16(float* d, uint32_t a0, uint32_t a1,
                                        uint32_t a2, uint32_t a3,
                                        uint32_t b0, uint32_t b1) {
    asm volatile(
        "mma.sync.aligned.m16n8k16.row.col.f32.f16.f16.f32 "
        "{%0,%1,%2,%3}, {%4,%5,%6,%7}, {%8,%9}, {%0,%1,%2,%3};"
        : "+f"(d[0]), "+f"(d[1]), "+f"(d[2]), "+f"(d[3])
        : "r"(a0), "r"(a1), "r"(a2), "r"(a3), "r"(b0), "r"(b1));
}
#define LDM_X4(r, addr) asm volatile( \
    "ldmatrix.sync.aligned.m8n8.x4.shared.b16 {%0,%1,%2,%3}, [%4];" \
    : "=r"((r)[0]), "=r"((r)[1]), "=r"((r)[2]), "=r"((r)[3]) : "r"(addr))

// ---------------------------------------------------------------------------
// Prep A: gemm W fragments as uint4 = {nt=2np:(r0,r1), nt=2np+1:(r0,r1)}
// ---------------------------------------------------------------------------
__global__ void __launch_bounds__(256) k_bfragG(const float* __restrict__ pk)
{
    int idx = blockIdx.x * 256 + threadIdx.x;     // < 5184
    if (idx >= 5184) return;
    int tap = idx / 192;
    int rem = idx - tap * 192;
    int np  = rem >> 5;
    int l   = rem & 31;
    int c0  = 2 * (l & 3);
    int n0  = 16 * np + (l >> 2);
    int n1  = n0 + 8;
    int kb  = tap * 16;
    float a0 = (n0 < 81) ? pk[(kb + c0    ) * 81 + n0] : 0.f;
    float a1 = (n0 < 81) ? pk[(kb + c0 + 1) * 81 + n0] : 0.f;
    float b0 = (n0 < 81) ? pk[(kb + c0 + 8) * 81 + n0] : 0.f;
    float b1 = (n0 < 81) ? pk[(kb + c0 + 9) * 81 + n0] : 0.f;
    float c2 = (n1 < 81) ? pk[(kb + c0    ) * 81 + n1] : 0.f;
    float c3 = (n1 < 81) ? pk[(kb + c0 + 1) * 81 + n1] : 0.f;
    float d2 = (n1 < 81) ? pk[(kb + c0 + 8) * 81 + n1] : 0.f;
    float d3 = (n1 < 81) ? pk[(kb + c0 + 9) * 81 + n1] : 0.f;
    __half2 h0 = __floats2half2_rn(a0, a1);
    __half2 h1 = __floats2half2_rn(b0, b1);
    __half2 h2 = __floats2half2_rn(c2, c3);
    __half2 h3 = __floats2half2_rn(d2, d3);
    g_BfragG[idx] = make_uint4(*reinterpret_cast<uint32_t*>(&h0),
                               *reinterpret_cast<uint32_t*>(&h1),
                               *reinterpret_cast<uint32_t*>(&h2),
                               *reinterpret_cast<uint32_t*>(&h3));
}

// ---------------------------------------------------------------------------
// Prep B: einsum kern fragments as uint4 {nt0:(lo,hi), nt1:(lo,hi)}
// ---------------------------------------------------------------------------
__global__ void __launch_bounds__(256) k_bfragD(const float* __restrict__ kern)
{
    int idx = blockIdx.x * 256 + threadIdx.x;     // < 864
    if (idx >= 864) return;
    int tap = idx >> 5;
    int l   = idx & 31;
    int c0  = 2 * (l & 3);
    int o0  = l >> 2;
    int kb  = tap * 16;
    __half2 h0 = __floats2half2_rn(kern[(kb + c0    ) * 16 + o0],
                                   kern[(kb + c0 + 1) * 16 + o0]);
    __half2 h1 = __floats2half2_rn(kern[(kb + c0 + 8) * 16 + o0],
                                   kern[(kb + c0 + 9) * 16 + o0]);
    __half2 h2 = __floats2half2_rn(kern[(kb + c0    ) * 16 + o0 + 8],
                                   kern[(kb + c0 + 1) * 16 + o0 + 8]);
    __half2 h3 = __floats2half2_rn(kern[(kb + c0 + 8) * 16 + o0 + 8],
                                   kern[(kb + c0 + 9) * 16 + o0 + 8]);
    g_BfragD[idx] = make_uint4(*reinterpret_cast<uint32_t*>(&h0),
                               *reinterpret_cast<uint32_t*>(&h1),
                               *reinterpret_cast<uint32_t*>(&h2),
                               *reinterpret_cast<uint32_t*>(&h3));
}

// ---------------------------------------------------------------------------
// Kernel 0: transpose x [c][v] -> fp16 channel-last [v][c]
// ---------------------------------------------------------------------------
__global__ void __launch_bounds__(256) k_transpose(const float* __restrict__ x)
{
    int v = blockIdx.x * 256 + threadIdx.x;
    float vals[16];
#pragma unroll
    for (int c = 0; c < 16; c++)
        vals[c] = x[(size_t)c * DHW + v];
    __half2 h[8];
#pragma unroll
    for (int i = 0; i < 8; i++)
        h[i] = __floats2half2_rn(vals[2*i], vals[2*i+1]);
    uint4* dst = reinterpret_cast<uint4*>(g_xth + (size_t)v * 8);
    dst[0] = *reinterpret_cast<uint4*>(&h[0]);
    dst[1] = *reinterpret_cast<uint4*>(&h[4]);
}

// ---------------------------------------------------------------------------
// Kernel 1: offset GEMM. Block = 128 voxels (z fixed, 2 y-rows, 64 x),
// 256 thr / 8 warps; warp = (m-group 0..3) x (N-half 0..1).
// SMEM: B phase buf (9 taps, 27648 B) @0; patch 38016 B @27648;
//       stage (51200 B) reuses @0. Total 65664 B -> 3/SM.
// Patch filled from g_xth (coalesced 16-B loads).
// ---------------------------------------------------------------------------
__global__ void __launch_bounds__(256, 3) k_gemm()
{
    extern __shared__ char smem[];
    const uint32_t smem_base = smem_u32(smem);
    uint4* bsm = reinterpret_cast<uint4*>(smem);               // B frags
    uint32_t* patch = reinterpret_cast<uint32_t*>(smem + 27648);
    float* stage = reinterpret_cast<float*>(smem);

    const int t    = threadIdx.x;
    const int lane = t & 31;
    const int w    = t >> 5;
    const int mg    = w >> 1;      // m-group: 32 voxels
    const int nhalf = w & 1;       // N half
    const int z    = blockIdx.y;
    const int y0   = blockIdx.x * 2;

    // x patch fp16 from g_xth: slot = (pz*4+py)*66+px, 2 uint4 @ pitch 48 B
    const uint4* xthq = reinterpret_cast<const uint4*>(g_xth);
    for (int j = t; j < 1584; j += 256) {
        int q    = j & 1;
        int slot = j >> 1;
        int px = slot % 66;
        int qq = slot / 66;
        int py = qq & 3, pz = qq >> 2;
        int gz = z - 1 + pz, gy = y0 - 1 + py, gx = px - 1;
        uint4 v = make_uint4(0u, 0u, 0u, 0u);
        if ((unsigned)gz < 64u && (unsigned)gy < 64u && (unsigned)gx < 64u)
            v = xthq[(size_t)(gz * HWs + gy * 64 + gx) * 2 + q];
        *reinterpret_cast<uint4*>(patch + slot * 12 + q * 4) = v;
    }

    // ldmatrix lane address bases (per m-tile)
    const int rowInTile = (lane & 7) + ((lane >> 3) & 1) * 8;
    const int khalf = lane >> 4;
    uint32_t abase[2];
#pragma unroll
    for (int mt = 0; mt < 2; mt++) {
        int r  = mg * 32 + mt * 16 + rowInTile;
        int sy = r >> 6, sx = r & 63;
        abase[mt] = smem_base + 27648u + (uint32_t)((sy * 66 + sx) * 48) + khalf * 16u;
    }

    float d[48];
#pragma unroll
    for (int i = 0; i < 48; i++) d[i] = 0.f;

#pragma unroll 1
    for (int phase = 0; phase < 3; phase++) {
        if (phase) __syncthreads();          // prev-phase B reads done
        for (int i = t; i < 1728; i += 256)
            bsm[i] = g_BfragG[phase * 1728 + i];
        __syncthreads();
#pragma unroll
        for (int tl = 0; tl < 9; tl++) {     // fully unrolled: aoff const-folded
            const int kh = tl / 3, kw = tl % 3;     // kd == phase
            const uint32_t aoff = (uint32_t)(((kh) * 66 + kw) * 48);
            uint32_t A0[4], A1[4];
            LDM_X4(A0, abase[0] + aoff);
            LDM_X4(A1, abase[1] + aoff);
            const uint4* bp = bsm + tl * 192 + nhalf * 96 + lane;
#pragma unroll
            for (int np = 0; np < 3; np++) {
                uint4 b = bp[np * 32];
                float* d0 = d + (np * 4    ) * 4;
                float* d1 = d + (np * 4 + 1) * 4;
                float* d2 = d + (np * 4 + 2) * 4;
                float* d3 = d + (np * 4 + 3) * 4;
                mma_f16(d0, A0[0], A0[1], A0[2], A0[3], b.x, b.y);
                mma_f16(d1, A1[0], A1[1], A1[2], A1[3], b.x, b.y);
                mma_f16(d2, A0[0], A0[1], A0[2], A0[3], b.z, b.w);
                mma_f16(d3, A1[0], A1[1], A1[2], A1[3], b.z, b.w);
            }
        }
        // advance A base by one z-plane of the patch (kd = phase)
        abase[0] += (uint32_t)(4 * 66 * 48);
        abase[1] += (uint32_t)(4 * 66 * 48);
    }
    __syncthreads();   // B + patch dead; reuse as stage

    // stage D: [128 vox][pitch 100]
    const int rlo  = lane >> 2;
    const int col0 = 2 * (lane & 3);
#pragma unroll
    for (int mt = 0; mt < 2; mt++) {
#pragma unroll
        for (int np = 0; np < 3; np++) {
#pragma unroll
            for (int ntl = 0; ntl < 2; ntl++) {
                const float* dd = d + ((np * 2 + ntl) * 2 + mt) * 4;
                int lr0 = mg * 32 + mt * 16 + rlo;
                int col = (2 * (nhalf * 3 + np) + ntl) * 8 + col0;
                stage[lr0 * 100 + col    ] = dd[0];
                stage[lr0 * 100 + col + 1] = dd[1];
                stage[(lr0 + 8) * 100 + col    ] = dd[2];
                stage[(lr0 + 8) * 100 + col + 1] = dd[3];
            }
        }
    }
    __syncthreads();

    // coalesced tap-major fp16 offset writes
    for (int i = t; i < 3456; i += 256) {
        int tap = i >> 7;
        int v   = i & 127;
        int vox = z * HWs + (y0 + (v >> 6)) * 64 + (v & 63);
        const float* s = stage + v * 100 + 3 * tap;
        __half2 h0 = __floats2half2_rn(s[0], s[1]);
        __half2 h1 = __floats2half2_rn(s[2], 0.f);
        g_offh[(size_t)tap * DHW + vox] =
            make_uint2(*reinterpret_cast<uint32_t*>(&h0),
                       *reinterpret_cast<uint32_t*>(&h1));
    }
}

// ---------------------------------------------------------------------------
// Kernel 2: deformable gather (half2 interp, split-plane region) + HMMA einsum.
// Block: 8x8x8 = 512 voxels, 16 warps.
// SMEM: region 2 planes x [13][13][13] x 16 B @0 (70304 B);
//       kern frags 13824 B @70304; A stage 16 warps x 1024 B @84128.
//       Total 100512 B -> 2 blocks/SM.
// A-stage layout [mt][khalf][16 rows x 16 B]: dense STS (4 wf) and
// conflict-free ldmatrix (rows at 16-B stride).
// ---------------------------------------------------------------------------
__global__ void __launch_bounds__(512, 2) k_deform(float* __restrict__ out)
{
    extern __shared__ char smem[];
    const uint4* xrq = reinterpret_cast<const uint4*>(smem);   // 2 x 2197 uint4
    const uint4* bfr = reinterpret_cast<const uint4*>(smem + 70304);
    const uint32_t smem_base = smem_u32(smem);

    const int t    = threadIdx.x;
    const int lane = t & 31;
    const int w    = t >> 5;

    // kern fragments -> smem (864 uint4)
    {
        uint4* bd = reinterpret_cast<uint4*>(smem + 70304);
        for (int i = t; i < 864; i += 512) bd[i] = g_BfragD[i];
    }

    const int bz = blockIdx.z * 8, by = blockIdx.y * 8, bx = blockIdx.x * 8;
    const int roz = bz - 2, roy = by - 2, rox = bx - 2;

    // region: 2197 points x 2 planes (ch0-7, ch8-15), 16 B each
    {
        const uint4* xthq = reinterpret_cast<const uint4*>(g_xth);
        uint4* xw = reinterpret_cast<uint4*>(smem);
        for (int u = t; u < 4394; u += 512) {
            int q = u & 1;      // plane
            int p = u >> 1;     // point
            int rx = p % 13;
            int p2 = p / 13;
            int ry = p2 % 13;
            int rz = p2 / 13;
            int gz = roz + rz, gy = roy + ry, gx = rox + rx;
            uint4 v = make_uint4(0u, 0u, 0u, 0u);
            if ((unsigned)gz < 64u && (unsigned)gy < 64u && (unsigned)gx < 64u)
                v = xthq[(size_t)(gz * HWs + gy * 64 + gx) * 2 + q];
            xw[q * 2197 + p] = v;
        }
    }
    __syncthreads();

    const int lx = t & 7, ly = (t >> 3) & 7, lz = t >> 6;   // lz 0..7
    const int pz = bz + lz, py = by + ly, px = bx + lx;
    const int vox = pz * HWs + py * 64 + px;
    const uint2* offp = g_offh + vox;

    // A-stage: per-warp 1024 B, layout [mt(lane>>4)][khalf][row(lane&15)*16]
    const uint32_t asb = 84128u + (uint32_t)w * 1024u;
    const uint32_t rowbase = asb + ((uint32_t)(lane >> 4)) * 512u
                           + (uint32_t)(lane & 15) * 16u;
    uint4* st0 = reinterpret_cast<uint4*>(smem + rowbase);          // khalf0
    uint4* st1 = reinterpret_cast<uint4*>(smem + rowbase + 256);    // khalf1
    const uint32_t addrA0 = smem_base + asb + (uint32_t)(lane & 15) * 16u
                          + (uint32_t)(lane >> 4) * 256u;
    const uint32_t addrA1 = addrA0 + 512u;

    float d[16];
#pragma unroll
    for (int q = 0; q < 16; q++) d[q] = 0.f;

    int kd = 0, kh = 0, kw = 0;
#pragma unroll 1
    for (int k = 0; k < 27; k++) {
        uint2 ob = offp[(size_t)k * DHW];
        float2 ozy = __half22float2(*reinterpret_cast<__half2*>(&ob.x));
        float2 oxp = __half22float2(*reinterpret_cast<__half2*>(&ob.y));
        float cz = (float)(pz + kd - 1) + ozy.x;
        float cy = (float)(py + kh - 1) + ozy.y;
        float cx = (float)(px + kw - 1) + oxp.x;
        if (++kw == 3) { kw = 0; if (++kh == 3) { kh = 0; ++kd; } }

        float z0f = floorf(cz), y0f = floorf(cy), x0f = floorf(cx);
        float fz = cz - z0f, fy = cy - y0f, fx = cx - x0f;
        int z0 = (int)z0f, y0 = (int)y0f, x0 = (int)x0f;
        int lz0 = z0 - roz, ly0 = y0 - roy, lx0 = x0 - rox;

        const __half2 wx0h = __float2half2_rn(1.f - fx);
        const __half2 wx1h = __float2half2_rn(fx);

        __half2 ah[8];
#pragma unroll
        for (int j = 0; j < 8; j++) ah[j] = __float2half2_rn(0.f);

        if ((unsigned)lz0 <= 11u && (unsigned)ly0 <= 11u && (unsigned)lx0 <= 11u) {
            // fast path: both x-corners inside region (zero-padded OOB)
#pragma unroll
            for (int dz = 0; dz < 2; dz++) {
                float wz = dz ? fz : 1.f - fz;
#pragma unroll
                for (int dy = 0; dy < 2; dy++) {
                    __half2 wzyh = __float2half2_rn(wz * (dy ? fy : 1.f - fy));
                    const int pt = (lz0 + dz) * 169 + (ly0 + dy) * 13 + lx0;
                    uint4 p0 = xrq[pt];            // ch0-7  @x0
                    uint4 q0 = xrq[pt + 1];        // ch0-7  @x1
                    uint4 p1 = xrq[2197 + pt];     // ch8-15 @x0
                    uint4 q1 = xrq[2197 + pt + 1]; // ch8-15 @x1
#pragma unroll
                    for (int j = 0; j < 4; j++) {
                        __half2 pj = *(reinterpret_cast<__half2*>(&p0) + j);
                        __half2 qj = *(reinterpret_cast<__half2*>(&q0) + j);
                        __half2 tj = __hfma2(qj, wx1h, __hmul2(pj, wx0h));
                        ah[j] = __hfma2(tj, wzyh, ah[j]);
                        __half2 pk2 = *(reinterpret_cast<__half2*>(&p1) + j);
                        __half2 qk2 = *(reinterpret_cast<__half2*>(&q1) + j);
                        __half2 uk = __hfma2(qk2, wx1h, __hmul2(pk2, wx0h));
                        ah[j + 4] = __hfma2(uk, wzyh, ah[j + 4]);
                    }
                }
            }
        } else {
            // exact fallback: per-corner validity, global fp16 reads
#pragma unroll
            for (int dz = 0; dz < 2; dz++) {
                float wz = dz ? fz : 1.f - fz;
#pragma unroll
                for (int dy = 0; dy < 2; dy++) {
                    __half2 wzyh = __float2half2_rn(wz * (dy ? fy : 1.f - fy));
                    int zi = z0 + dz, yi = y0 + dy;
                    bool okzy = ((unsigned)zi < 64u) && ((unsigned)yi < 64u);
                    uint4 p0 = make_uint4(0,0,0,0), p1 = p0, q0 = p0, q1 = p0;
                    if (okzy && (unsigned)x0 < 64u) {
                        const uint4* g = reinterpret_cast<const uint4*>(
                            g_xth + (size_t)(zi * HWs + yi * 64 + x0) * 8);
                        p0 = g[0]; p1 = g[1];
                    }
                    if (okzy && (unsigned)(x0 + 1) < 64u) {
                        const uint4* g = reinterpret_cast<const uint4*>(
                            g_xth + (size_t)(zi * HWs + yi * 64 + x0 + 1) * 8);
                        q0 = g[0]; q1 = g[1];
                    }
#pragma unroll
                    for (int j = 0; j < 4; j++) {
                        __half2 pj = *(reinterpret_cast<__half2*>(&p0) + j);
                        __half2 qj = *(reinterpret_cast<__half2*>(&q0) + j);
                        __half2 tj = __hfma2(qj, wx1h, __hmul2(pj, wx0h));
                        ah[j] = __hfma2(tj, wzyh, ah[j]);
                        __half2 pk2 = *(reinterpret_cast<__half2*>(&p1) + j);
                        __half2 qk2 = *(reinterpret_cast<__half2*>(&q1) + j);
                        __half2 uk = __hfma2(qk2, wx1h, __hmul2(pk2, wx0h));
                        ah[j + 4] = __hfma2(uk, wzyh, ah[j + 4]);
                    }
                }
            }
        }

        // ---- einsum via HMMA: stage ah -> ldmatrix -> mma ----
        __syncwarp();                       // WAR vs previous tap's ldmatrix
        st0[0] = *reinterpret_cast<uint4*>(&ah[0]);
        st1[0] = *reinterpret_cast<uint4*>(&ah[4]);
        __syncwarp();                       // RAW
        uint32_t A0[4], A1[4];
        LDM_X4(A0, addrA0);
        LDM_X4(A1, addrA1);
        uint4 b = bfr[k * 32 + lane];
        mma_f16(d,      A0[0], A0[1], A0[2], A0[3], b.x, b.y);
        mma_f16(d + 8,  A1[0], A1[1], A1[2], A1[3], b.x, b.y);
        mma_f16(d + 4,  A0[0], A0[1], A0[2], A0[3], b.z, b.w);
        mma_f16(d + 12, A1[0], A1[1], A1[2], A1[3], b.z, b.w);
    }

    // ---- write out ----
    const int rlo = lane >> 2;
    const int o0  = 2 * (lane & 3);
#pragma unroll
    for (int mt = 0; mt < 2; mt++) {
#pragma unroll
        for (int nt = 0; nt < 2; nt++) {
            const float* dd = d + mt * 8 + nt * 4;
            int vlo = mt * 16 + rlo;
            int vhi = vlo + 8;
            int vox_lo = (bz + (w >> 1)) * HWs
                       + (by + (w & 1) * 4 + (vlo >> 3)) * 64 + bx + (vlo & 7);
            int vox_hi = (bz + (w >> 1)) * HWs
                       + (by + (w & 1) * 4 + (vhi >> 3)) * 64 + bx + (vhi & 7);
            out[(size_t)(nt * 8 + o0    ) * DHW + vox_lo] = dd[0];
            out[(size_t)(nt * 8 + o0 + 1) * DHW + vox_lo] = dd[1];
            out[(size_t)(nt * 8 + o0    ) * DHW + vox_hi] = dd[2];
            out[(size_t)(nt * 8 + o0 + 1) * DHW + vox_hi] = dd[3];
        }
    }
}

// ---------------------------------------------------------------------------
extern "C" void kernel_launch(void* const* d_in, const int* in_sizes, int n_in,
                              void* d_out, int out_size)
{
    const float* x    = (const float*)d_in[0];   // [16,64,64,64]
    const float* kern = (const float*)d_in[1];   // [27,16,16]
    const float* pk   = (const float*)d_in[2];   // [27,16,81]
    float* out = (float*)d_out;                  // [16,64,64,64]

    cudaFuncSetAttribute(k_gemm,   cudaFuncAttributeMaxDynamicSharedMemorySize, 65664);
    cudaFuncSetAttribute(k_deform, cudaFuncAttributeMaxDynamicSharedMemorySize, 100512);

    k_bfragG<<<21, 256>>>(pk);
    k_bfragD<<<4, 256>>>(kern);
    k_transpose<<<1024, 256>>>(x);
    k_gemm<<<dim3(32, 64), 256, 65664>>>();
    k_deform<<<dim3(8, 8, 8), 512, 100512>>>(out);
}